// round 1
// baseline (speedup 1.0000x reference)
#include <cuda_runtime.h>
#include <math.h>

// Problem constants
#define NB 4
#define NS 2048
#define ND 1024
#define NH 8
#define NHD 128
#define NFF 512
#define NE 8
#define NT 65536            // B*S*H token-heads
#define NROWS 8192          // B*S
#define MU_C 0.7f
#define LN_EPS_C 1e-5f

// Scratch (static device globals: allocation-free per harness rules)
__device__ float g_t[(size_t)NROWS * ND];     // split output == t [NT][NHD]
__device__ float g_eo[(size_t)NT * NHD];      // expert outputs (atomic accum)
__device__ float g_ln[(size_t)NROWS * ND];    // post-LN, input to merge
__device__ int   g_cnt[NE];
__device__ int   g_elist[NE * NT];
__device__ float g_ew[NE * NT];

// ---------------------------------------------------------------------------
// Tiled SGEMM with bias: C[M,N] = A[M,K] @ B[K,N] + bias[N]
// BM=BN=128, BK=16, 256 threads, 8x8 per-thread micro-tile.
// ---------------------------------------------------------------------------
__global__ __launch_bounds__(256, 2)
void sgemm_bias_kernel(const float* __restrict__ A, const float* __restrict__ B,
                       const float* __restrict__ bias, float* __restrict__ C,
                       int M, int N, int K)
{
    __shared__ float As[16][128];   // transposed: As[k][m]
    __shared__ float Bs[16][128];   // Bs[k][n]

    const int m0 = blockIdx.y * 128;
    const int n0 = blockIdx.x * 128;
    const int t  = threadIdx.x;
    const int tr = t >> 4;          // 0..15
    const int tc = t & 15;          // 0..15
    const int arow = t >> 2;        // 0..63
    const int ac   = (t & 3) * 4;   // 0,4,8,12
    const int brow = t >> 5;        // 0..7
    const int bc   = (t & 31) * 4;  // 0..124

    float acc[8][8];
#pragma unroll
    for (int i = 0; i < 8; ++i)
#pragma unroll
        for (int j = 0; j < 8; ++j) acc[i][j] = 0.f;

    for (int k0 = 0; k0 < K; k0 += 16) {
#pragma unroll
        for (int h = 0; h < 2; ++h) {
            const int r = arow + h * 64;
            const float4 v = *reinterpret_cast<const float4*>(
                A + (size_t)(m0 + r) * K + k0 + ac);
            As[ac + 0][r] = v.x; As[ac + 1][r] = v.y;
            As[ac + 2][r] = v.z; As[ac + 3][r] = v.w;
        }
#pragma unroll
        for (int h = 0; h < 2; ++h) {
            const int r = brow + h * 8;
            *reinterpret_cast<float4*>(&Bs[r][bc]) =
                *reinterpret_cast<const float4*>(B + (size_t)(k0 + r) * N + n0 + bc);
        }
        __syncthreads();

#pragma unroll
        for (int kk = 0; kk < 16; ++kk) {
            float ra[8], rb[8];
            *reinterpret_cast<float4*>(ra)     = *reinterpret_cast<const float4*>(&As[kk][tr * 8]);
            *reinterpret_cast<float4*>(ra + 4) = *reinterpret_cast<const float4*>(&As[kk][tr * 8 + 4]);
            *reinterpret_cast<float4*>(rb)     = *reinterpret_cast<const float4*>(&Bs[kk][tc * 8]);
            *reinterpret_cast<float4*>(rb + 4) = *reinterpret_cast<const float4*>(&Bs[kk][tc * 8 + 4]);
#pragma unroll
            for (int i = 0; i < 8; ++i)
#pragma unroll
                for (int j = 0; j < 8; ++j)
                    acc[i][j] += ra[i] * rb[j];
        }
        __syncthreads();
    }

#pragma unroll
    for (int i = 0; i < 8; ++i) {
        const int gm = m0 + tr * 8 + i;
#pragma unroll
        for (int j = 0; j < 8; j += 4) {
            const int gn = n0 + tc * 8 + j;
            float4 o;
            o.x = acc[i][j + 0] + bias[gn + 0];
            o.y = acc[i][j + 1] + bias[gn + 1];
            o.z = acc[i][j + 2] + bias[gn + 2];
            o.w = acc[i][j + 3] + bias[gn + 3];
            *reinterpret_cast<float4*>(C + (size_t)gm * N + gn) = o;
        }
    }
}

// ---------------------------------------------------------------------------
// Gate: logits = t @ gate_W + gate_b; top-2 + softmax; build per-expert lists.
// One warp per token (8 tokens / 256-thread block).
// ---------------------------------------------------------------------------
__global__ __launch_bounds__(256)
void gate_kernel(const float* __restrict__ gW, const float* __restrict__ gb)
{
    __shared__ float sW[NHD * NE];
    const int tid = threadIdx.x;
    for (int i = tid; i < NHD * NE; i += 256) sW[i] = gW[i];
    __syncthreads();

    const int lane = tid & 31, warp = tid >> 5;
    const int token = blockIdx.x * 8 + warp;

    const float4 tv = *reinterpret_cast<const float4*>(g_t + (size_t)token * NHD + lane * 4);
    float lg[NE];
#pragma unroll
    for (int e = 0; e < NE; ++e) {
        const int d = lane * 4;
        lg[e] = tv.x * sW[(d + 0) * NE + e] + tv.y * sW[(d + 1) * NE + e]
              + tv.z * sW[(d + 2) * NE + e] + tv.w * sW[(d + 3) * NE + e];
    }
#pragma unroll
    for (int off = 16; off; off >>= 1)
#pragma unroll
        for (int e = 0; e < NE; ++e)
            lg[e] += __shfl_xor_sync(0xffffffffu, lg[e], off);

    if (lane == 0) {
        float v0 = -1e30f, v1 = -1e30f;
        int i0 = 0, i1 = 0;
#pragma unroll
        for (int e = 0; e < NE; ++e) {
            const float v = lg[e] + gb[e];
            if (v > v0) { v0 = v; i0 = e; }
        }
#pragma unroll
        for (int e = 0; e < NE; ++e) {
            const float v = lg[e] + gb[e];
            if (e != i0 && v > v1) { v1 = v; i1 = e; }
        }
        const float w0 = 1.f / (1.f + expf(v1 - v0));
        const float w1 = 1.f - w0;
        int p = atomicAdd(&g_cnt[i0], 1);
        g_elist[i0 * NT + p] = token; g_ew[i0 * NT + p] = w0;
        p = atomicAdd(&g_cnt[i1], 1);
        g_elist[i1 * NT + p] = token; g_ew[i1 * NT + p] = w1;
    }
}

// ---------------------------------------------------------------------------
// Fused expert kernel. Block = (expert e, tile of 128 tokens from e's list).
// Computes y = gate_w * (relu(A @ W1_e + b1_e) @ W2_e + b2_e) fully in SMEM,
// chunking FF=512 into 4 chunks of 128. Scatter-add into g_eo via atomics.
// Dynamic smem: As 64KB + Ws 64KB + Hs 64.5KB + lists = 198144 B (1 CTA/SM).
// ---------------------------------------------------------------------------
#define EXP_SMEM_FLOATS (16384 + 16384 + (129 * 128) + 128 + 128)
#define EXP_SMEM_BYTES  (EXP_SMEM_FLOATS * 4)

__global__ __launch_bounds__(256, 1)
void expert_kernel(const float* __restrict__ W1, const float* __restrict__ b1,
                   const float* __restrict__ W2, const float* __restrict__ b2)
{
    extern __shared__ float sm[];
    float* As  = sm;                     // As[k][m], ld 128 (transposed A)
    float* Ws  = sm + 16384;             // weight chunk [128][128]
    float* Hs  = sm + 32768;             // Hs[ff][m], ld 129 (transposed H)
    int*   srow = reinterpret_cast<int*>(sm + 32768 + 129 * 128);
    float* sgw  = sm + 32768 + 129 * 128 + 128;

    const int e  = blockIdx.y;
    const int tb = blockIdx.x * 128;
    const int cnt = g_cnt[e];
    if (tb >= cnt) return;
    const int nrows = min(128, cnt - tb);
    const int t = threadIdx.x;

    if (t < 128) {
        const bool v = t < nrows;
        srow[t] = v ? g_elist[e * NT + tb + t] : -1;
        sgw[t]  = v ? g_ew[e * NT + tb + t] : 0.f;
    }
    __syncthreads();

    // Gather token rows into As (transposed). 2 threads per row, 64 cols each.
    {
        const int m = t >> 1, k0 = (t & 1) * 64;
        const int r = srow[m];
        const float* src = g_t + (size_t)(r < 0 ? 0 : r) * NHD + k0;
#pragma unroll
        for (int i = 0; i < 16; ++i) {
            float4 v = (r >= 0) ? *reinterpret_cast<const float4*>(src + 4 * i)
                                : make_float4(0.f, 0.f, 0.f, 0.f);
            const int k = k0 + 4 * i;
            As[(k + 0) * 128 + m] = v.x; As[(k + 1) * 128 + m] = v.y;
            As[(k + 2) * 128 + m] = v.z; As[(k + 3) * 128 + m] = v.w;
        }
    }

    const int tr = t >> 4, tc = t & 15;
    float acc[8][8];
#pragma unroll
    for (int i = 0; i < 8; ++i)
#pragma unroll
        for (int j = 0; j < 8; ++j) acc[i][j] = 0.f;

    for (int fc = 0; fc < 4; ++fc) {
        __syncthreads();   // gather done (iter 0) / previous Hs+Ws readers done

        // Load W1 chunk: Ws[k][n] = W1[e][k][fc*128 + n]
#pragma unroll
        for (int i = 0; i < 16; ++i) {
            const int idx = t + i * 256;
            const int row = idx >> 5, col = (idx & 31) * 4;
            *reinterpret_cast<float4*>(&Ws[row * 128 + col]) =
                *reinterpret_cast<const float4*>(
                    W1 + (size_t)(e * NHD + row) * NFF + fc * 128 + col);
        }
        __syncthreads();

        // GEMM1: H = A @ W1c  (K = 128)
        float h[8][8];
#pragma unroll
        for (int i = 0; i < 8; ++i)
#pragma unroll
            for (int j = 0; j < 8; ++j) h[i][j] = 0.f;

#pragma unroll 4
        for (int kk = 0; kk < 128; ++kk) {
            float ra[8], rb[8];
            *reinterpret_cast<float4*>(ra)     = *reinterpret_cast<const float4*>(&As[kk * 128 + tr * 8]);
            *reinterpret_cast<float4*>(ra + 4) = *reinterpret_cast<const float4*>(&As[kk * 128 + tr * 8 + 4]);
            *reinterpret_cast<float4*>(rb)     = *reinterpret_cast<const float4*>(&Ws[kk * 128 + tc * 8]);
            *reinterpret_cast<float4*>(rb + 4) = *reinterpret_cast<const float4*>(&Ws[kk * 128 + tc * 8 + 4]);
#pragma unroll
            for (int i = 0; i < 8; ++i)
#pragma unroll
                for (int j = 0; j < 8; ++j)
                    h[i][j] += ra[i] * rb[j];
        }

        // bias + relu, store transposed into Hs[ff][m] (ld 129)
#pragma unroll
        for (int j = 0; j < 8; ++j) {
            const float bv = b1[e * NFF + fc * 128 + tc * 8 + j];
#pragma unroll
            for (int i = 0; i < 8; ++i) {
                float v = h[i][j] + bv;
                v = v > 0.f ? v : 0.f;
                Hs[(tc * 8 + j) * 129 + tr * 8 + i] = v;
            }
        }
        __syncthreads();

        // Load W2 chunk: Ws[ff][d] = W2[e][fc*128 + ff][d]
#pragma unroll
        for (int i = 0; i < 16; ++i) {
            const int idx = t + i * 256;
            const int row = idx >> 5, col = (idx & 31) * 4;
            *reinterpret_cast<float4*>(&Ws[row * 128 + col]) =
                *reinterpret_cast<const float4*>(
                    W2 + (size_t)(e * NFF + fc * 128 + row) * NHD + col);
        }
        __syncthreads();

        // GEMM2: Y += H @ W2c  (K = 128 over ff)
#pragma unroll 4
        for (int kk = 0; kk < 128; ++kk) {
            float ra[8], rb[8];
#pragma unroll
            for (int i = 0; i < 8; ++i) ra[i] = Hs[kk * 129 + tr * 8 + i];
            *reinterpret_cast<float4*>(rb)     = *reinterpret_cast<const float4*>(&Ws[kk * 128 + tc * 8]);
            *reinterpret_cast<float4*>(rb + 4) = *reinterpret_cast<const float4*>(&Ws[kk * 128 + tc * 8 + 4]);
#pragma unroll
            for (int i = 0; i < 8; ++i)
#pragma unroll
                for (int j = 0; j < 8; ++j)
                    acc[i][j] += ra[i] * rb[j];
        }
    }

    // Epilogue: scatter-add gate_w * (Y + b2) into g_eo
#pragma unroll
    for (int i = 0; i < 8; ++i) {
        const int m = tr * 8 + i;
        const int r = srow[m];
        if (r < 0) continue;
        const float w = sgw[m];
#pragma unroll
        for (int j = 0; j < 8; ++j) {
            const int d = tc * 8 + j;
            atomicAdd(&g_eo[(size_t)r * NHD + d], w * (acc[i][j] + b2[e * NHD + d]));
        }
    }
}

// ---------------------------------------------------------------------------
// Momentum update + LayerNorm over head_dim. One warp per token.
// new_momentum = -expert_out + 0.7*momentum ; out = t + new_momentum ; LN(out)
// ---------------------------------------------------------------------------
__global__ __launch_bounds__(256)
void ln_mom_kernel(const float* __restrict__ mom_in,
                   const float* __restrict__ ln_g, const float* __restrict__ ln_b,
                   float* __restrict__ mom_out, int write_mom)
{
    const int tid = threadIdx.x;
    const int lane = tid & 31, warp = tid >> 5;
    const int token = blockIdx.x * 8 + warp;
    const size_t base = (size_t)token * NHD + lane * 4;

    const float4 tv = *reinterpret_cast<const float4*>(g_t + base);
    const float4 ev = *reinterpret_cast<const float4*>(g_eo + base);
    const float4 mv = *reinterpret_cast<const float4*>(mom_in + base);

    float nm[4] = { -ev.x + MU_C * mv.x, -ev.y + MU_C * mv.y,
                    -ev.z + MU_C * mv.z, -ev.w + MU_C * mv.w };
    if (write_mom) {
        float4 o; o.x = nm[0]; o.y = nm[1]; o.z = nm[2]; o.w = nm[3];
        *reinterpret_cast<float4*>(mom_out + base) = o;
    }

    float o[4] = { tv.x + nm[0], tv.y + nm[1], tv.z + nm[2], tv.w + nm[3] };
    float s1 = o[0] + o[1] + o[2] + o[3];
    float s2 = o[0] * o[0] + o[1] * o[1] + o[2] * o[2] + o[3] * o[3];
#pragma unroll
    for (int off = 16; off; off >>= 1) {
        s1 += __shfl_xor_sync(0xffffffffu, s1, off);
        s2 += __shfl_xor_sync(0xffffffffu, s2, off);
    }
    const float mean = s1 * (1.f / NHD);
    const float var  = s2 * (1.f / NHD) - mean * mean;
    const float rstd = rsqrtf(var + LN_EPS_C);

    const float4 gv = *reinterpret_cast<const float4*>(ln_g + lane * 4);
    const float4 bv = *reinterpret_cast<const float4*>(ln_b + lane * 4);
    float4 r;
    r.x = (o[0] - mean) * rstd * gv.x + bv.x;
    r.y = (o[1] - mean) * rstd * gv.y + bv.y;
    r.z = (o[2] - mean) * rstd * gv.z + bv.z;
    r.w = (o[3] - mean) * rstd * gv.w + bv.w;
    *reinterpret_cast<float4*>(g_ln + base) = r;
}

// ---------------------------------------------------------------------------
extern "C" void kernel_launch(void* const* d_in, const int* in_sizes, int n_in,
                              void* d_out, int out_size)
{
    const float* x       = (const float*)d_in[0];
    const float* mom_in  = (const float*)d_in[1];
    const float* split_W = (const float*)d_in[2];
    const float* split_b = (const float*)d_in[3];
    const float* gate_W  = (const float*)d_in[4];
    const float* gate_b  = (const float*)d_in[5];
    const float* W1      = (const float*)d_in[6];
    const float* b1      = (const float*)d_in[7];
    const float* W2      = (const float*)d_in[8];
    const float* b2      = (const float*)d_in[9];
    const float* ln_g    = (const float*)d_in[10];
    const float* ln_b    = (const float*)d_in[11];
    const float* merge_W = (const float*)d_in[12];
    const float* merge_b = (const float*)d_in[13];

    float* out = (float*)d_out;
    const int write_mom = (out_size >= 2 * NROWS * ND) ? 1 : 0;
    float* mom_out = out + (size_t)NROWS * ND;

    void *p_eo = nullptr, *p_cnt = nullptr, *p_t = nullptr, *p_ln = nullptr;
    cudaGetSymbolAddress(&p_eo, g_eo);
    cudaGetSymbolAddress(&p_cnt, g_cnt);
    cudaGetSymbolAddress(&p_t, g_t);
    cudaGetSymbolAddress(&p_ln, g_ln);

    cudaMemsetAsync(p_eo, 0, sizeof(float) * (size_t)NT * NHD);
    cudaMemsetAsync(p_cnt, 0, sizeof(int) * NE);

    cudaFuncSetAttribute(expert_kernel, cudaFuncAttributeMaxDynamicSharedMemorySize,
                         EXP_SMEM_BYTES);

    dim3 gg(ND / 128, NROWS / 128);   // (8, 64)

    // 1) split: t = x @ split_W + split_b
    sgemm_bias_kernel<<<gg, 256>>>(x, split_W, split_b, (float*)p_t, NROWS, ND, ND);

    // 2) gate: top-2 + per-expert token lists
    gate_kernel<<<NT / 8, 256>>>(gate_W, gate_b);

    // 3) sparse expert compute (top-2 only; identical math to dense reference)
    expert_kernel<<<dim3(NT / 128, NE), 256, EXP_SMEM_BYTES>>>(W1, b1, W2, b2);

    // 4) momentum + layernorm (also writes new_momentum output)
    ln_mom_kernel<<<NT / 8, 256>>>(mom_in, ln_g, ln_b, mom_out, write_mom);

    // 5) merge: final = ln_out @ merge_W + merge_b
    sgemm_bias_kernel<<<gg, 256>>>((const float*)p_ln, merge_W, merge_b, out,
                                   NROWS, ND, ND);
}

// round 3
// speedup vs baseline: 1.9755x; 1.9755x over previous
#include <cuda_runtime.h>
#include <math.h>
#include <stdint.h>

// Problem constants
#define NB 4
#define NS 2048
#define ND 1024
#define NH 8
#define NHD 128
#define NFF 512
#define NE 8
#define NT 65536            // B*S*H token-heads
#define NROWS 8192          // B*S
#define MU_C 0.7f
#define LN_EPS_C 1e-5f

// Scratch (static device globals)
__device__ float g_t[(size_t)NROWS * ND];     // split output == t [NT][NHD]
__device__ float g_eo[(size_t)NT * NHD];      // expert outputs (atomic accum)
__device__ float g_ln[(size_t)NROWS * ND];    // post-LN, input to merge
__device__ float g_lg[(size_t)NT * NE];       // gate logits [T][E]
__device__ float g_mg[ND * NH * NE];          // fused gate matrix [D][64]
__device__ float g_bg[NH * NE];               // fused gate bias  [64]
__device__ int   g_cnt[NE];
__device__ int   g_elist[NE * NT];
__device__ float g_ew[NE * NT];

// ===========================================================================
// Helpers
// ===========================================================================
__device__ __forceinline__ uint32_t f2tf32(float v) {
    uint32_t o;
    asm("cvt.rna.tf32.f32 %0, %1;" : "=r"(o) : "f"(v));
    return o;
}

__device__ __forceinline__ void mma8(float* c, const uint32_t* a, const uint32_t* b) {
    asm volatile(
        "mma.sync.aligned.m16n8k8.row.col.f32.tf32.tf32.f32 "
        "{%0,%1,%2,%3}, {%4,%5,%6,%7}, {%8,%9}, {%0,%1,%2,%3};"
        : "+f"(c[0]), "+f"(c[1]), "+f"(c[2]), "+f"(c[3])
        : "r"(a[0]), "r"(a[1]), "r"(a[2]), "r"(a[3]), "r"(b[0]), "r"(b[1]));
}

// One k8 step for a 64x32 warp tile (4 m16 x 4 n8 fragments).
// As: [m][lda] tf32 (m-major), Bs: [k][ldb] tf32 (k rows, n cols).
__device__ __forceinline__ void mma_tile_step(
    const uint32_t* __restrict__ As, int lda, int a_k,
    const uint32_t* __restrict__ Bs, int ldb, int b_k,
    int warp_m, int warp_n, int gid, int tig, float acc[4][4][4])
{
    uint32_t a[4][4], b[4][2];
#pragma unroll
    for (int mt = 0; mt < 4; ++mt) {
        const uint32_t* p = As + (warp_m + mt * 16 + gid) * lda + a_k + tig;
        a[mt][0] = p[0];
        a[mt][1] = p[8 * lda];
        a[mt][2] = p[4];
        a[mt][3] = p[8 * lda + 4];
    }
#pragma unroll
    for (int nt = 0; nt < 4; ++nt) {
        const uint32_t* p = Bs + (b_k + tig) * ldb + warp_n + nt * 8 + gid;
        b[nt][0] = p[0];
        b[nt][1] = p[4 * ldb];
    }
#pragma unroll
    for (int mt = 0; mt < 4; ++mt)
#pragma unroll
        for (int nt = 0; nt < 4; ++nt)
            mma8(acc[mt][nt], a[mt], b[nt]);
}

__device__ __forceinline__ void sts_tf32_4(uint32_t* dst, float4 v) {
    dst[0] = f2tf32(v.x); dst[1] = f2tf32(v.y);
    dst[2] = f2tf32(v.z); dst[3] = f2tf32(v.w);
}

extern __shared__ char dynsm[];

// ===========================================================================
// Warp-MMA tf32 GEMM with bias: C[M,N] = A[M,K] @ B[K,N] + bias[N]
// CTA 128x128, BK=16, double-buffered, 256 threads (8 warps 2x4).
// ===========================================================================
#define GLDA 20
#define GLDB 132
#define GAS0 0
#define GAS1 2560
#define GBS0 5120
#define GBS1 7232
#define GSMEM_BYTES (9344 * 4)

__global__ __launch_bounds__(256, 2)
void mma_gemm_kernel(const float* __restrict__ A, const float* __restrict__ B,
                     const float* __restrict__ bias, float* __restrict__ C,
                     int M, int N, int K)
{
    uint32_t* smu = reinterpret_cast<uint32_t*>(dynsm);
    const int t = threadIdx.x;
    const int wid = t >> 5, lane = t & 31;
    const int gid = lane >> 2, tig = lane & 3;
    const int warp_m = (wid >> 2) * 64, warp_n = (wid & 3) * 32;
    const int m0 = blockIdx.y * 128, n0 = blockIdx.x * 128;

    const int ar = t >> 1, akc = (t & 1) * 8;
    const int bkr = t >> 4, bnc = (t & 15) * 8;
    const float* Aptr = A + (size_t)(m0 + ar) * K + akc;
    const float* Bptr = B + (size_t)bkr * N + n0 + bnc;
    const size_t bstep = (size_t)16 * N;

    float acc[4][4][4];
#pragma unroll
    for (int i = 0; i < 4; ++i)
#pragma unroll
        for (int j = 0; j < 4; ++j)
#pragma unroll
            for (int k = 0; k < 4; ++k) acc[i][j][k] = 0.f;

    float4 pa0, pa1, pb0, pb1;
    pa0 = *reinterpret_cast<const float4*>(Aptr);
    pa1 = *reinterpret_cast<const float4*>(Aptr + 4);
    pb0 = *reinterpret_cast<const float4*>(Bptr);
    pb1 = *reinterpret_cast<const float4*>(Bptr + 4);
    sts_tf32_4(smu + GAS0 + ar * GLDA + akc, pa0);
    sts_tf32_4(smu + GAS0 + ar * GLDA + akc + 4, pa1);
    sts_tf32_4(smu + GBS0 + bkr * GLDB + bnc, pb0);
    sts_tf32_4(smu + GBS0 + bkr * GLDB + bnc + 4, pb1);
    __syncthreads();

    const int KI = K >> 4;
    for (int it = 0; it < KI; ++it) {
        const int s = it & 1;
        const bool more = (it + 1 < KI);
        if (more) {
            pa0 = *reinterpret_cast<const float4*>(Aptr + (it + 1) * 16);
            pa1 = *reinterpret_cast<const float4*>(Aptr + (it + 1) * 16 + 4);
            pb0 = *reinterpret_cast<const float4*>(Bptr + (size_t)(it + 1) * bstep);
            pb1 = *reinterpret_cast<const float4*>(Bptr + (size_t)(it + 1) * bstep + 4);
        }
        const uint32_t* As = smu + (s ? GAS1 : GAS0);
        const uint32_t* Bs = smu + (s ? GBS1 : GBS0);
        mma_tile_step(As, GLDA, 0, Bs, GLDB, 0, warp_m, warp_n, gid, tig, acc);
        mma_tile_step(As, GLDA, 8, Bs, GLDB, 8, warp_m, warp_n, gid, tig, acc);
        if (more) {
            uint32_t* Ad = smu + (s ? GAS0 : GAS1);
            uint32_t* Bd = smu + (s ? GBS0 : GBS1);
            sts_tf32_4(Ad + ar * GLDA + akc, pa0);
            sts_tf32_4(Ad + ar * GLDA + akc + 4, pa1);
            sts_tf32_4(Bd + bkr * GLDB + bnc, pb0);
            sts_tf32_4(Bd + bkr * GLDB + bnc + 4, pb1);
        }
        __syncthreads();
    }

    // Epilogue
#pragma unroll
    for (int mt = 0; mt < 4; ++mt) {
        const int r0 = m0 + warp_m + mt * 16 + gid;
        const int r1 = r0 + 8;
#pragma unroll
        for (int nt = 0; nt < 4; ++nt) {
            const int col = n0 + warp_n + nt * 8 + 2 * tig;
            const float b0v = bias[col], b1v = bias[col + 1];
            float2 s0, s1;
            s0.x = acc[mt][nt][0] + b0v; s0.y = acc[mt][nt][1] + b1v;
            s1.x = acc[mt][nt][2] + b0v; s1.y = acc[mt][nt][3] + b1v;
            *reinterpret_cast<float2*>(C + (size_t)r0 * N + col) = s0;
            *reinterpret_cast<float2*>(C + (size_t)r1 * N + col) = s1;
        }
    }
}

// ===========================================================================
// Expert kernel with warp MMA. Block = (expert e, tile of 128 tokens).
// y = gate_w * (relu(A @ W1_e + b1) @ W2_e + b2), scatter-add to g_eo.
// ===========================================================================
#define ELD 132
#define E_AT 0
#define E_H  16896
#define E_W0 33792
#define E_W1 38016
#define E_ROW 42240
#define E_GW  42368
#define E_SMEM_BYTES (42496 * 4)

__global__ __launch_bounds__(256, 1)
void expert_kernel(const float* __restrict__ W1, const float* __restrict__ b1,
                   const float* __restrict__ W2, const float* __restrict__ b2)
{
    uint32_t* smu = reinterpret_cast<uint32_t*>(dynsm);
    uint32_t* sAt = smu + E_AT;
    uint32_t* sH  = smu + E_H;
    int*   srow = reinterpret_cast<int*>(smu + E_ROW);
    float* sgw  = reinterpret_cast<float*>(smu + E_GW);

    const int e  = blockIdx.y;
    const int tb = blockIdx.x * 128;
    const int cnt = g_cnt[e];
    if (tb >= cnt) return;
    const int nrows = min(128, cnt - tb);
    const int t = threadIdx.x;
    const int wid = t >> 5, lane = t & 31;
    const int gid = lane >> 2, tig = lane & 3;
    const int warp_m = (wid >> 2) * 64, warp_n = (wid & 3) * 32;

    if (t < 128) {
        const bool v = t < nrows;
        srow[t] = v ? g_elist[e * NT + tb + t] : -1;
        sgw[t]  = v ? g_ew[e * NT + tb + t] : 0.f;
    }
    __syncthreads();

    // Gather token rows into sAt (m-major tf32). 2 threads/row, 64 cols each.
    {
        const int m = t >> 1, k0 = (t & 1) * 64;
        const int r = srow[m];
        const float* src = g_t + (size_t)(r < 0 ? 0 : r) * NHD + k0;
        uint32_t* dst = sAt + m * ELD + k0;
#pragma unroll
        for (int i = 0; i < 16; ++i) {
            float4 v = (r >= 0) ? *reinterpret_cast<const float4*>(src + 4 * i)
                                : make_float4(0.f, 0.f, 0.f, 0.f);
            sts_tf32_4(dst + 4 * i, v);
        }
    }

    // W slice load mapping: 32 rows x 128 cols per slice
    const int wkr = t >> 3, wnc = (t & 7) * 16;

    float y_acc[4][4][4];
#pragma unroll
    for (int i = 0; i < 4; ++i)
#pragma unroll
        for (int j = 0; j < 4; ++j)
#pragma unroll
            for (int k = 0; k < 4; ++k) y_acc[i][j][k] = 0.f;

    for (int fc = 0; fc < 4; ++fc) {
        // ---------------- GEMM1: H = A @ W1c ----------------
        float4 pw[4];
        {
            const float* src = W1 + ((size_t)(e * NHD + wkr) * NFF) + fc * 128 + wnc;
#pragma unroll
            for (int i = 0; i < 4; ++i)
                pw[i] = *reinterpret_cast<const float4*>(src + 4 * i);
        }
        {
            uint32_t* dst = smu + E_W0 + wkr * ELD + wnc;
#pragma unroll
            for (int i = 0; i < 4; ++i) sts_tf32_4(dst + 4 * i, pw[i]);
        }
        __syncthreads();   // covers A gather (fc=0), sW free, sH free

        float h_acc[4][4][4];
#pragma unroll
        for (int i = 0; i < 4; ++i)
#pragma unroll
            for (int j = 0; j < 4; ++j)
#pragma unroll
                for (int k = 0; k < 4; ++k) h_acc[i][j][k] = 0.f;

        for (int kt = 0; kt < 4; ++kt) {
            const int s = kt & 1;
            if (kt < 3) {
                const float* src = W1 + ((size_t)(e * NHD + (kt + 1) * 32 + wkr) * NFF)
                                 + fc * 128 + wnc;
#pragma unroll
                for (int i = 0; i < 4; ++i)
                    pw[i] = *reinterpret_cast<const float4*>(src + 4 * i);
            }
            const uint32_t* Ws = smu + (s ? E_W1 : E_W0);
#pragma unroll
            for (int k8 = 0; k8 < 4; ++k8)
                mma_tile_step(sAt, ELD, kt * 32 + k8 * 8, Ws, ELD, k8 * 8,
                              warp_m, warp_n, gid, tig, h_acc);
            if (kt < 3) {
                uint32_t* dst = smu + (s ? E_W0 : E_W1) + wkr * ELD + wnc;
#pragma unroll
                for (int i = 0; i < 4; ++i) sts_tf32_4(dst + 4 * i, pw[i]);
            }
            __syncthreads();
        }

        // bias + relu -> sH (tf32)
#pragma unroll
        for (int mt = 0; mt < 4; ++mt) {
            const int r0 = warp_m + mt * 16 + gid;
#pragma unroll
            for (int nt = 0; nt < 4; ++nt) {
                const int col = warp_n + nt * 8 + 2 * tig;
                const float bv0 = b1[e * NFF + fc * 128 + col];
                const float bv1 = b1[e * NFF + fc * 128 + col + 1];
                float v0 = h_acc[mt][nt][0] + bv0; v0 = v0 > 0.f ? v0 : 0.f;
                float v1 = h_acc[mt][nt][1] + bv1; v1 = v1 > 0.f ? v1 : 0.f;
                float v2 = h_acc[mt][nt][2] + bv0; v2 = v2 > 0.f ? v2 : 0.f;
                float v3 = h_acc[mt][nt][3] + bv1; v3 = v3 > 0.f ? v3 : 0.f;
                sH[r0 * ELD + col]           = f2tf32(v0);
                sH[r0 * ELD + col + 1]       = f2tf32(v1);
                sH[(r0 + 8) * ELD + col]     = f2tf32(v2);
                sH[(r0 + 8) * ELD + col + 1] = f2tf32(v3);
            }
        }

        // ---------------- GEMM2: Y += H @ W2c ----------------
        {
            const float* src = W2 + ((size_t)(e * NFF + fc * 128 + wkr) * NHD) + wnc;
#pragma unroll
            for (int i = 0; i < 4; ++i)
                pw[i] = *reinterpret_cast<const float4*>(src + 4 * i);
        }
        __syncthreads();   // sH visible; sW buffers free
        {
            uint32_t* dst = smu + E_W0 + wkr * ELD + wnc;
#pragma unroll
            for (int i = 0; i < 4; ++i) sts_tf32_4(dst + 4 * i, pw[i]);
        }
        __syncthreads();

        for (int kt = 0; kt < 4; ++kt) {
            const int s = kt & 1;
            if (kt < 3) {
                const float* src = W2 + ((size_t)(e * NFF + fc * 128 + (kt + 1) * 32 + wkr) * NHD)
                                 + wnc;
#pragma unroll
                for (int i = 0; i < 4; ++i)
                    pw[i] = *reinterpret_cast<const float4*>(src + 4 * i);
            }
            const uint32_t* Ws = smu + (s ? E_W1 : E_W0);
#pragma unroll
            for (int k8 = 0; k8 < 4; ++k8)
                mma_tile_step(sH, ELD, kt * 32 + k8 * 8, Ws, ELD, k8 * 8,
                              warp_m, warp_n, gid, tig, y_acc);
            if (kt < 3) {
                uint32_t* dst = smu + (s ? E_W0 : E_W1) + wkr * ELD + wnc;
#pragma unroll
                for (int i = 0; i < 4; ++i) sts_tf32_4(dst + 4 * i, pw[i]);
            }
            __syncthreads();
        }
    }

    // Scatter epilogue: atomicAdd gate_w * (Y + b2)
#pragma unroll
    for (int mt = 0; mt < 4; ++mt) {
        const int m0_ = warp_m + mt * 16 + gid;
        const int rA = srow[m0_], rB = srow[m0_ + 8];
        const float wA = sgw[m0_], wB = sgw[m0_ + 8];
#pragma unroll
        for (int nt = 0; nt < 4; ++nt) {
            const int col = warp_n + nt * 8 + 2 * tig;
            const float b0v = b2[e * NHD + col];
            const float b1v = b2[e * NHD + col + 1];
            if (rA >= 0) {
                atomicAdd(&g_eo[(size_t)rA * NHD + col],     wA * (y_acc[mt][nt][0] + b0v));
                atomicAdd(&g_eo[(size_t)rA * NHD + col + 1], wA * (y_acc[mt][nt][1] + b1v));
            }
            if (rB >= 0) {
                atomicAdd(&g_eo[(size_t)rB * NHD + col],     wB * (y_acc[mt][nt][2] + b0v));
                atomicAdd(&g_eo[(size_t)rB * NHD + col + 1], wB * (y_acc[mt][nt][3] + b1v));
            }
        }
    }
}

// ===========================================================================
// Gate path (exact fp32 routing)
// ===========================================================================
__global__ __launch_bounds__(256)
void mg_prep_kernel(const float* __restrict__ sW, const float* __restrict__ gW)
{
    __shared__ float sg[NHD * NE];
    const int tid = threadIdx.x;
    for (int i = tid; i < NHD * NE; i += 256) sg[i] = gW[i];
    __syncthreads();
    const int idx = blockIdx.x * 256 + tid;
    const int d = idx >> 6, he = idx & 63;
    const int h = he >> 3, e = he & 7;
    const float* wrow = sW + (size_t)d * ND + h * NHD;
    float s = 0.f;
#pragma unroll 8
    for (int j = 0; j < NHD; ++j) s += wrow[j] * sg[j * NE + e];
    g_mg[d * 64 + he] = s;
}

__global__ void gate_bias_kernel(const float* __restrict__ sb_,
                                 const float* __restrict__ gW,
                                 const float* __restrict__ gb)
{
    const int he = threadIdx.x;
    const int h = he >> 3, e = he & 7;
    float s = gb[e];
    for (int j = 0; j < NHD; ++j) s += sb_[h * NHD + j] * gW[j * NE + e];
    g_bg[he] = s;
}

__global__ __launch_bounds__(256, 2)
void gate_gemm_kernel(const float* __restrict__ A)
{
    __shared__ float As[16][64];
    __shared__ float Bs[16][64];
    const int m0 = blockIdx.x * 64;
    const int t = threadIdx.x;
    const int tr = t >> 4, tc = t & 15;

    float acc[4][4];
#pragma unroll
    for (int i = 0; i < 4; ++i)
#pragma unroll
        for (int j = 0; j < 4; ++j) acc[i][j] = 0.f;

    for (int k0 = 0; k0 < ND; k0 += 16) {
        {
            const int row = t >> 2, kc = (t & 3) * 4;
            const float4 v = *reinterpret_cast<const float4*>(
                A + (size_t)(m0 + row) * ND + k0 + kc);
            As[kc + 0][row] = v.x; As[kc + 1][row] = v.y;
            As[kc + 2][row] = v.z; As[kc + 3][row] = v.w;
        }
        {
            const int row = t >> 4, col = (t & 15) * 4;
            *reinterpret_cast<float4*>(&Bs[row][col]) =
                *reinterpret_cast<const float4*>(g_mg + (size_t)(k0 + row) * 64 + col);
        }
        __syncthreads();
#pragma unroll
        for (int kk = 0; kk < 16; ++kk) {
            float ra[4], rb[4];
            *reinterpret_cast<float4*>(ra) = *reinterpret_cast<const float4*>(&As[kk][tr * 4]);
            *reinterpret_cast<float4*>(rb) = *reinterpret_cast<const float4*>(&Bs[kk][tc * 4]);
#pragma unroll
            for (int i = 0; i < 4; ++i)
#pragma unroll
                for (int j = 0; j < 4; ++j)
                    acc[i][j] += ra[i] * rb[j];
        }
        __syncthreads();
    }
#pragma unroll
    for (int i = 0; i < 4; ++i) {
        const int row = m0 + tr * 4 + i;
#pragma unroll
        for (int j = 0; j < 4; ++j) {
            const int col = tc * 4 + j;
            g_lg[(size_t)row * 64 + col] = acc[i][j] + g_bg[col];
        }
    }
}

__global__ __launch_bounds__(256)
void topk_kernel()
{
    const int token = blockIdx.x * 256 + threadIdx.x;
    const float* l = g_lg + (size_t)token * NE;
    float v[NE];
    const float4 a = *reinterpret_cast<const float4*>(l);
    const float4 b = *reinterpret_cast<const float4*>(l + 4);
    v[0] = a.x; v[1] = a.y; v[2] = a.z; v[3] = a.w;
    v[4] = b.x; v[5] = b.y; v[6] = b.z; v[7] = b.w;

    float v0 = -1e30f, v1 = -1e30f;
    int i0 = 0, i1 = 0;
#pragma unroll
    for (int e = 0; e < NE; ++e)
        if (v[e] > v0) { v0 = v[e]; i0 = e; }
#pragma unroll
    for (int e = 0; e < NE; ++e)
        if (e != i0 && v[e] > v1) { v1 = v[e]; i1 = e; }
    const float w0 = 1.f / (1.f + expf(v1 - v0));
    const float w1 = 1.f - w0;
    int p = atomicAdd(&g_cnt[i0], 1);
    g_elist[i0 * NT + p] = token; g_ew[i0 * NT + p] = w0;
    p = atomicAdd(&g_cnt[i1], 1);
    g_elist[i1 * NT + p] = token; g_ew[i1 * NT + p] = w1;
}

// ===========================================================================
// Momentum + LayerNorm
// ===========================================================================
__global__ __launch_bounds__(256)
void ln_mom_kernel(const float* __restrict__ mom_in,
                   const float* __restrict__ ln_g, const float* __restrict__ ln_b,
                   float* __restrict__ mom_out, int write_mom)
{
    const int tid = threadIdx.x;
    const int lane = tid & 31, warp = tid >> 5;
    const int token = blockIdx.x * 8 + warp;
    const size_t base = (size_t)token * NHD + lane * 4;

    const float4 tv = *reinterpret_cast<const float4*>(g_t + base);
    const float4 ev = *reinterpret_cast<const float4*>(g_eo + base);
    const float4 mv = *reinterpret_cast<const float4*>(mom_in + base);

    float nm[4] = { -ev.x + MU_C * mv.x, -ev.y + MU_C * mv.y,
                    -ev.z + MU_C * mv.z, -ev.w + MU_C * mv.w };
    if (write_mom) {
        float4 o; o.x = nm[0]; o.y = nm[1]; o.z = nm[2]; o.w = nm[3];
        *reinterpret_cast<float4*>(mom_out + base) = o;
    }

    float o[4] = { tv.x + nm[0], tv.y + nm[1], tv.z + nm[2], tv.w + nm[3] };
    float s1 = o[0] + o[1] + o[2] + o[3];
    float s2 = o[0] * o[0] + o[1] * o[1] + o[2] * o[2] + o[3] * o[3];
#pragma unroll
    for (int off = 16; off; off >>= 1) {
        s1 += __shfl_xor_sync(0xffffffffu, s1, off);
        s2 += __shfl_xor_sync(0xffffffffu, s2, off);
    }
    const float mean = s1 * (1.f / NHD);
    const float var  = s2 * (1.f / NHD) - mean * mean;
    const float rstd = rsqrtf(var + LN_EPS_C);

    const float4 gv = *reinterpret_cast<const float4*>(ln_g + lane * 4);
    const float4 bv = *reinterpret_cast<const float4*>(ln_b + lane * 4);
    float4 r;
    r.x = (o[0] - mean) * rstd * gv.x + bv.x;
    r.y = (o[1] - mean) * rstd * gv.y + bv.y;
    r.z = (o[2] - mean) * rstd * gv.z + bv.z;
    r.w = (o[3] - mean) * rstd * gv.w + bv.w;
    *reinterpret_cast<float4*>(g_ln + base) = r;
}

// ---------------------------------------------------------------------------
extern "C" void kernel_launch(void* const* d_in, const int* in_sizes, int n_in,
                              void* d_out, int out_size)
{
    const float* x       = (const float*)d_in[0];
    const float* mom_in  = (const float*)d_in[1];
    const float* split_W = (const float*)d_in[2];
    const float* split_b = (const float*)d_in[3];
    const float* gate_W  = (const float*)d_in[4];
    const float* gate_b  = (const float*)d_in[5];
    const float* W1      = (const float*)d_in[6];
    const float* b1      = (const float*)d_in[7];
    const float* W2      = (const float*)d_in[8];
    const float* b2      = (const float*)d_in[9];
    const float* ln_g    = (const float*)d_in[10];
    const float* ln_b    = (const float*)d_in[11];
    const float* merge_W = (const float*)d_in[12];
    const float* merge_b = (const float*)d_in[13];

    float* out = (float*)d_out;
    const int write_mom = (out_size >= 2 * NROWS * ND) ? 1 : 0;
    float* mom_out = out + (size_t)NROWS * ND;

    void *p_eo = nullptr, *p_cnt = nullptr, *p_t = nullptr, *p_ln = nullptr;
    cudaGetSymbolAddress(&p_eo, g_eo);
    cudaGetSymbolAddress(&p_cnt, g_cnt);
    cudaGetSymbolAddress(&p_t, g_t);
    cudaGetSymbolAddress(&p_ln, g_ln);

    cudaMemsetAsync(p_eo, 0, sizeof(float) * (size_t)NT * NHD);
    cudaMemsetAsync(p_cnt, 0, sizeof(int) * NE);

    cudaFuncSetAttribute(expert_kernel, cudaFuncAttributeMaxDynamicSharedMemorySize,
                         E_SMEM_BYTES);
    cudaFuncSetAttribute(mma_gemm_kernel, cudaFuncAttributeMaxDynamicSharedMemorySize,
                         GSMEM_BYTES);

    // Exact-fp32 gate routing
    mg_prep_kernel<<<256, 256>>>(split_W, gate_W);
    gate_bias_kernel<<<1, 64>>>(split_b, gate_W, gate_b);
    gate_gemm_kernel<<<NROWS / 64, 256>>>(x);
    topk_kernel<<<NT / 256, 256>>>();

    // split: t = x @ split_W + split_b
    mma_gemm_kernel<<<dim3(ND / 128, NROWS / 128), 256, GSMEM_BYTES>>>(
        x, split_W, split_b, (float*)p_t, NROWS, ND, ND);

    // sparse expert compute (top-2 only)
    expert_kernel<<<dim3(NT / 128, NE), 256, E_SMEM_BYTES>>>(W1, b1, W2, b2);

    // momentum + layernorm
    ln_mom_kernel<<<NT / 8, 256>>>(mom_in, ln_g, ln_b, mom_out, write_mom);

    // merge: final = ln_out @ merge_W + merge_b
    mma_gemm_kernel<<<dim3(ND / 128, NROWS / 128), 256, GSMEM_BYTES>>>(
        (const float*)p_ln, merge_W, merge_b, out, NROWS, ND, ND);
}

// round 5
// speedup vs baseline: 2.0531x; 1.0393x over previous
#include <cuda_runtime.h>
#include <math.h>
#include <stdint.h>

// Problem constants
#define NB 4
#define NS 2048
#define ND 1024
#define NH 8
#define NHD 128
#define NFF 512
#define NE 8
#define NT 65536            // B*S*H token-heads
#define NROWS 8192          // B*S
#define MU_C 0.7f
#define LN_EPS_C 1e-5f

// Scratch (static device globals)
__device__ float g_t[(size_t)NROWS * ND];     // split output == t [NT][NHD]
__device__ float g_eo2[(size_t)NT * 2 * NHD]; // expert outputs, 2 slots/token
__device__ float g_ln[(size_t)NROWS * ND];    // post-LN, input to merge
__device__ float g_lg[(size_t)NT * NE];       // gate logits [T][E]
__device__ float g_mg[ND * NH * NE];          // fused gate matrix [D][64]
__device__ float g_bg[NH * NE];               // fused gate bias  [64]
__device__ int   g_cnt[NE];
__device__ int   g_elist[NE * NT];            // token*2 + slot
__device__ float g_ew[NE * NT];

// ===========================================================================
// Helpers
// ===========================================================================
__device__ __forceinline__ uint32_t f2tf32(float v) {
    uint32_t o;
    asm("cvt.rna.tf32.f32 %0, %1;" : "=r"(o) : "f"(v));
    return o;
}

__device__ __forceinline__ void mma8(float* c, const uint32_t* a, const uint32_t* b) {
    asm volatile(
        "mma.sync.aligned.m16n8k8.row.col.f32.tf32.tf32.f32 "
        "{%0,%1,%2,%3}, {%4,%5,%6,%7}, {%8,%9}, {%0,%1,%2,%3};"
        : "+f"(c[0]), "+f"(c[1]), "+f"(c[2]), "+f"(c[3])
        : "r"(a[0]), "r"(a[1]), "r"(a[2]), "r"(a[3]), "r"(b[0]), "r"(b[1]));
}

// One k8 step for a 64x32 warp tile (4 m16 x 4 n8 fragments).
// As: [m][lda] tf32 (m-major), Bs: [k][ldb] tf32 (k rows, n cols).
__device__ __forceinline__ void mma_tile_step(
    const uint32_t* __restrict__ As, int lda, int a_k,
    const uint32_t* __restrict__ Bs, int ldb, int b_k,
    int warp_m, int warp_n, int gid, int tig, float acc[4][4][4])
{
    uint32_t a[4][4], b[4][2];
#pragma unroll
    for (int mt = 0; mt < 4; ++mt) {
        const uint32_t* p = As + (warp_m + mt * 16 + gid) * lda + a_k + tig;
        a[mt][0] = p[0];
        a[mt][1] = p[8 * lda];
        a[mt][2] = p[4];
        a[mt][3] = p[8 * lda + 4];
    }
#pragma unroll
    for (int nt = 0; nt < 4; ++nt) {
        const uint32_t* p = Bs + (b_k + tig) * ldb + warp_n + nt * 8 + gid;
        b[nt][0] = p[0];
        b[nt][1] = p[4 * ldb];
    }
#pragma unroll
    for (int mt = 0; mt < 4; ++mt)
#pragma unroll
        for (int nt = 0; nt < 4; ++nt)
            mma8(acc[mt][nt], a[mt], b[nt]);
}

__device__ __forceinline__ void sts_tf32_4(uint32_t* dst, float4 v) {
    dst[0] = f2tf32(v.x); dst[1] = f2tf32(v.y);
    dst[2] = f2tf32(v.z); dst[3] = f2tf32(v.w);
}

extern __shared__ char dynsm[];

// ===========================================================================
// Warp-MMA tf32 GEMM with bias: C[M,N] = A[M,K] @ B[K,N] + bias[N]
// CTA 128x128, BK=16, double-buffered, 256 threads (8 warps 2x4).
// ===========================================================================
#define GLDA 20
#define GLDB 132
#define GAS0 0
#define GAS1 2560
#define GBS0 5120
#define GBS1 7232
#define GSMEM_BYTES (9344 * 4)

__global__ __launch_bounds__(256, 2)
void mma_gemm_kernel(const float* __restrict__ A, const float* __restrict__ B,
                     const float* __restrict__ bias, float* __restrict__ C,
                     int M, int N, int K)
{
    uint32_t* smu = reinterpret_cast<uint32_t*>(dynsm);
    const int t = threadIdx.x;
    const int wid = t >> 5, lane = t & 31;
    const int gid = lane >> 2, tig = lane & 3;
    const int warp_m = (wid >> 2) * 64, warp_n = (wid & 3) * 32;
    const int m0 = blockIdx.y * 128, n0 = blockIdx.x * 128;

    const int ar = t >> 1, akc = (t & 1) * 8;
    const int bkr = t >> 4, bnc = (t & 15) * 8;
    const float* Aptr = A + (size_t)(m0 + ar) * K + akc;
    const float* Bptr = B + (size_t)bkr * N + n0 + bnc;
    const size_t bstep = (size_t)16 * N;

    float acc[4][4][4];
#pragma unroll
    for (int i = 0; i < 4; ++i)
#pragma unroll
        for (int j = 0; j < 4; ++j)
#pragma unroll
            for (int k = 0; k < 4; ++k) acc[i][j][k] = 0.f;

    float4 pa0, pa1, pb0, pb1;
    pa0 = *reinterpret_cast<const float4*>(Aptr);
    pa1 = *reinterpret_cast<const float4*>(Aptr + 4);
    pb0 = *reinterpret_cast<const float4*>(Bptr);
    pb1 = *reinterpret_cast<const float4*>(Bptr + 4);
    sts_tf32_4(smu + GAS0 + ar * GLDA + akc, pa0);
    sts_tf32_4(smu + GAS0 + ar * GLDA + akc + 4, pa1);
    sts_tf32_4(smu + GBS0 + bkr * GLDB + bnc, pb0);
    sts_tf32_4(smu + GBS0 + bkr * GLDB + bnc + 4, pb1);
    __syncthreads();

    const int KI = K >> 4;
    for (int it = 0; it < KI; ++it) {
        const int s = it & 1;
        const bool more = (it + 1 < KI);
        if (more) {
            pa0 = *reinterpret_cast<const float4*>(Aptr + (it + 1) * 16);
            pa1 = *reinterpret_cast<const float4*>(Aptr + (it + 1) * 16 + 4);
            pb0 = *reinterpret_cast<const float4*>(Bptr + (size_t)(it + 1) * bstep);
            pb1 = *reinterpret_cast<const float4*>(Bptr + (size_t)(it + 1) * bstep + 4);
        }
        const uint32_t* As = smu + (s ? GAS1 : GAS0);
        const uint32_t* Bs = smu + (s ? GBS1 : GBS0);
        mma_tile_step(As, GLDA, 0, Bs, GLDB, 0, warp_m, warp_n, gid, tig, acc);
        mma_tile_step(As, GLDA, 8, Bs, GLDB, 8, warp_m, warp_n, gid, tig, acc);
        if (more) {
            uint32_t* Ad = smu + (s ? GAS0 : GAS1);
            uint32_t* Bd = smu + (s ? GBS0 : GBS1);
            sts_tf32_4(Ad + ar * GLDA + akc, pa0);
            sts_tf32_4(Ad + ar * GLDA + akc + 4, pa1);
            sts_tf32_4(Bd + bkr * GLDB + bnc, pb0);
            sts_tf32_4(Bd + bkr * GLDB + bnc + 4, pb1);
        }
        __syncthreads();
    }

    // Epilogue
#pragma unroll
    for (int mt = 0; mt < 4; ++mt) {
        const int r0 = m0 + warp_m + mt * 16 + gid;
        const int r1 = r0 + 8;
#pragma unroll
        for (int nt = 0; nt < 4; ++nt) {
            const int col = n0 + warp_n + nt * 8 + 2 * tig;
            const float b0v = bias[col], b1v = bias[col + 1];
            float2 s0, s1;
            s0.x = acc[mt][nt][0] + b0v; s0.y = acc[mt][nt][1] + b1v;
            s1.x = acc[mt][nt][2] + b0v; s1.y = acc[mt][nt][3] + b1v;
            *reinterpret_cast<float2*>(C + (size_t)r0 * N + col) = s0;
            *reinterpret_cast<float2*>(C + (size_t)r1 * N + col) = s1;
        }
    }
}

// ===========================================================================
// Expert kernel with warp MMA. Block = (expert e, tile of 128 tokens).
// y = gate_w * (relu(A @ W1_e + b1) @ W2_e + b2); plain STG to per-slot rows.
// ===========================================================================
#define ELD 132
#define E_AT 0
#define E_H  16896
#define E_W0 33792
#define E_W1 38016
#define E_ROW 42240
#define E_GW  42368
#define E_SMEM_BYTES (42496 * 4)

__global__ __launch_bounds__(256, 1)
void expert_kernel(const float* __restrict__ W1, const float* __restrict__ b1,
                   const float* __restrict__ W2, const float* __restrict__ b2)
{
    uint32_t* smu = reinterpret_cast<uint32_t*>(dynsm);
    uint32_t* sAt = smu + E_AT;
    uint32_t* sH  = smu + E_H;
    int*   srow = reinterpret_cast<int*>(smu + E_ROW);
    float* sgw  = reinterpret_cast<float*>(smu + E_GW);

    const int e  = blockIdx.y;
    const int tb = blockIdx.x * 128;
    const int cnt = g_cnt[e];
    if (tb >= cnt) return;
    const int nrows = min(128, cnt - tb);
    const int t = threadIdx.x;
    const int wid = t >> 5, lane = t & 31;
    const int gid = lane >> 2, tig = lane & 3;
    const int warp_m = (wid >> 2) * 64, warp_n = (wid & 3) * 32;

    if (t < 128) {
        const bool v = t < nrows;
        srow[t] = v ? g_elist[e * NT + tb + t] : -1;   // token*2 + slot
        sgw[t]  = v ? g_ew[e * NT + tb + t] : 0.f;
    }
    __syncthreads();

    // Gather token rows into sAt (m-major tf32). 2 threads/row, 64 cols each.
    {
        const int m = t >> 1, k0 = (t & 1) * 64;
        const int r = srow[m];
        const int token = (r < 0) ? 0 : (r >> 1);
        const float* src = g_t + (size_t)token * NHD + k0;
        uint32_t* dst = sAt + m * ELD + k0;
#pragma unroll
        for (int i = 0; i < 16; ++i) {
            float4 v = (r >= 0) ? *reinterpret_cast<const float4*>(src + 4 * i)
                                : make_float4(0.f, 0.f, 0.f, 0.f);
            sts_tf32_4(dst + 4 * i, v);
        }
    }

    // W slice load mapping: 32 rows x 128 cols per slice
    const int wkr = t >> 3, wnc = (t & 7) * 16;

    float y_acc[4][4][4];
#pragma unroll
    for (int i = 0; i < 4; ++i)
#pragma unroll
        for (int j = 0; j < 4; ++j)
#pragma unroll
            for (int k = 0; k < 4; ++k) y_acc[i][j][k] = 0.f;

    for (int fc = 0; fc < 4; ++fc) {
        // ---------------- GEMM1: H = A @ W1c ----------------
        float4 pw[4];
        {
            const float* src = W1 + ((size_t)(e * NHD + wkr) * NFF) + fc * 128 + wnc;
#pragma unroll
            for (int i = 0; i < 4; ++i)
                pw[i] = *reinterpret_cast<const float4*>(src + 4 * i);
        }
        {
            uint32_t* dst = smu + E_W0 + wkr * ELD + wnc;
#pragma unroll
            for (int i = 0; i < 4; ++i) sts_tf32_4(dst + 4 * i, pw[i]);
        }
        __syncthreads();   // covers A gather (fc=0), sW free, sH free

        float h_acc[4][4][4];
#pragma unroll
        for (int i = 0; i < 4; ++i)
#pragma unroll
            for (int j = 0; j < 4; ++j)
#pragma unroll
                for (int k = 0; k < 4; ++k) h_acc[i][j][k] = 0.f;

        for (int kt = 0; kt < 4; ++kt) {
            const int s = kt & 1;
            if (kt < 3) {
                const float* src = W1 + ((size_t)(e * NHD + (kt + 1) * 32 + wkr) * NFF)
                                 + fc * 128 + wnc;
#pragma unroll
                for (int i = 0; i < 4; ++i)
                    pw[i] = *reinterpret_cast<const float4*>(src + 4 * i);
            }
            const uint32_t* Ws = smu + (s ? E_W1 : E_W0);
#pragma unroll
            for (int k8 = 0; k8 < 4; ++k8)
                mma_tile_step(sAt, ELD, kt * 32 + k8 * 8, Ws, ELD, k8 * 8,
                              warp_m, warp_n, gid, tig, h_acc);
            if (kt < 3) {
                uint32_t* dst = smu + (s ? E_W0 : E_W1) + wkr * ELD + wnc;
#pragma unroll
                for (int i = 0; i < 4; ++i) sts_tf32_4(dst + 4 * i, pw[i]);
            }
            __syncthreads();
        }

        // bias + relu -> sH (tf32)
#pragma unroll
        for (int mt = 0; mt < 4; ++mt) {
            const int r0 = warp_m + mt * 16 + gid;
#pragma unroll
            for (int nt = 0; nt < 4; ++nt) {
                const int col = warp_n + nt * 8 + 2 * tig;
                const float bv0 = b1[e * NFF + fc * 128 + col];
                const float bv1 = b1[e * NFF + fc * 128 + col + 1];
                float v0 = h_acc[mt][nt][0] + bv0; v0 = v0 > 0.f ? v0 : 0.f;
                float v1 = h_acc[mt][nt][1] + bv1; v1 = v1 > 0.f ? v1 : 0.f;
                float v2 = h_acc[mt][nt][2] + bv0; v2 = v2 > 0.f ? v2 : 0.f;
                float v3 = h_acc[mt][nt][3] + bv1; v3 = v3 > 0.f ? v3 : 0.f;
                sH[r0 * ELD + col]           = f2tf32(v0);
                sH[r0 * ELD + col + 1]       = f2tf32(v1);
                sH[(r0 + 8) * ELD + col]     = f2tf32(v2);
                sH[(r0 + 8) * ELD + col + 1] = f2tf32(v3);
            }
        }

        // ---------------- GEMM2: Y += H @ W2c ----------------
        {
            const float* src = W2 + ((size_t)(e * NFF + fc * 128 + wkr) * NHD) + wnc;
#pragma unroll
            for (int i = 0; i < 4; ++i)
                pw[i] = *reinterpret_cast<const float4*>(src + 4 * i);
        }
        __syncthreads();   // sH visible; sW buffers free
        {
            uint32_t* dst = smu + E_W0 + wkr * ELD + wnc;
#pragma unroll
            for (int i = 0; i < 4; ++i) sts_tf32_4(dst + 4 * i, pw[i]);
        }
        __syncthreads();

        for (int kt = 0; kt < 4; ++kt) {
            const int s = kt & 1;
            if (kt < 3) {
                const float* src = W2 + ((size_t)(e * NFF + fc * 128 + (kt + 1) * 32 + wkr) * NHD)
                                 + wnc;
#pragma unroll
                for (int i = 0; i < 4; ++i)
                    pw[i] = *reinterpret_cast<const float4*>(src + 4 * i);
            }
            const uint32_t* Ws = smu + (s ? E_W1 : E_W0);
#pragma unroll
            for (int k8 = 0; k8 < 4; ++k8)
                mma_tile_step(sH, ELD, kt * 32 + k8 * 8, Ws, ELD, k8 * 8,
                              warp_m, warp_n, gid, tig, y_acc);
            if (kt < 3) {
                uint32_t* dst = smu + (s ? E_W0 : E_W1) + wkr * ELD + wnc;
#pragma unroll
                for (int i = 0; i < 4; ++i) sts_tf32_4(dst + 4 * i, pw[i]);
            }
            __syncthreads();
        }
    }

    // Epilogue: plain STG of gate_w * (Y + b2) into per-slot row (no atomics)
#pragma unroll
    for (int mt = 0; mt < 4; ++mt) {
        const int m0_ = warp_m + mt * 16 + gid;
        const int rA = srow[m0_], rB = srow[m0_ + 8];
        const float wA = sgw[m0_], wB = sgw[m0_ + 8];
#pragma unroll
        for (int nt = 0; nt < 4; ++nt) {
            const int col = warp_n + nt * 8 + 2 * tig;
            const float b0v = b2[e * NHD + col];
            const float b1v = b2[e * NHD + col + 1];
            if (rA >= 0) {
                float2 v;
                v.x = wA * (y_acc[mt][nt][0] + b0v);
                v.y = wA * (y_acc[mt][nt][1] + b1v);
                *reinterpret_cast<float2*>(&g_eo2[(size_t)rA * NHD + col]) = v;
            }
            if (rB >= 0) {
                float2 v;
                v.x = wB * (y_acc[mt][nt][2] + b0v);
                v.y = wB * (y_acc[mt][nt][3] + b1v);
                *reinterpret_cast<float2*>(&g_eo2[(size_t)rB * NHD + col]) = v;
            }
        }
    }
}

// ===========================================================================
// Gate path (exact fp32 routing)
// ===========================================================================
__global__ __launch_bounds__(256)
void mg_prep_kernel(const float* __restrict__ sW, const float* __restrict__ gW)
{
    __shared__ float sg[NHD * NE];
    const int tid = threadIdx.x;
    for (int i = tid; i < NHD * NE; i += 256) sg[i] = gW[i];
    __syncthreads();
    const int idx = blockIdx.x * 256 + tid;
    const int d = idx >> 6, he = idx & 63;
    const int h = he >> 3, e = he & 7;
    const float* wrow = sW + (size_t)d * ND + h * NHD;
    float s = 0.f;
#pragma unroll 8
    for (int j = 0; j < NHD; ++j) s += wrow[j] * sg[j * NE + e];
    g_mg[d * 64 + he] = s;
}

__global__ void gate_bias_kernel(const float* __restrict__ sb_,
                                 const float* __restrict__ gW,
                                 const float* __restrict__ gb)
{
    const int he = threadIdx.x;
    const int h = he >> 3, e = he & 7;
    float s = gb[e];
    for (int j = 0; j < NHD; ++j) s += sb_[h * NHD + j] * gW[j * NE + e];
    g_bg[he] = s;
}

__global__ __launch_bounds__(256, 2)
void gate_gemm_kernel(const float* __restrict__ A)
{
    __shared__ float As[16][64];
    __shared__ float Bs[16][64];
    const int m0 = blockIdx.x * 64;
    const int t = threadIdx.x;
    const int tr = t >> 4, tc = t & 15;

    float acc[4][4];
#pragma unroll
    for (int i = 0; i < 4; ++i)
#pragma unroll
        for (int j = 0; j < 4; ++j) acc[i][j] = 0.f;

    for (int k0 = 0; k0 < ND; k0 += 16) {
        {
            const int row = t >> 2, kc = (t & 3) * 4;
            const float4 v = *reinterpret_cast<const float4*>(
                A + (size_t)(m0 + row) * ND + k0 + kc);
            As[kc + 0][row] = v.x; As[kc + 1][row] = v.y;
            As[kc + 2][row] = v.z; As[kc + 3][row] = v.w;
        }
        {
            const int row = t >> 4, col = (t & 15) * 4;
            *reinterpret_cast<float4*>(&Bs[row][col]) =
                *reinterpret_cast<const float4*>(g_mg + (size_t)(k0 + row) * 64 + col);
        }
        __syncthreads();
#pragma unroll
        for (int kk = 0; kk < 16; ++kk) {
            float ra[4], rb[4];
            *reinterpret_cast<float4*>(ra) = *reinterpret_cast<const float4*>(&As[kk][tr * 4]);
            *reinterpret_cast<float4*>(rb) = *reinterpret_cast<const float4*>(&Bs[kk][tc * 4]);
#pragma unroll
            for (int i = 0; i < 4; ++i)
#pragma unroll
                for (int j = 0; j < 4; ++j)
                    acc[i][j] += ra[i] * rb[j];
        }
        __syncthreads();
    }
#pragma unroll
    for (int i = 0; i < 4; ++i) {
        const int row = m0 + tr * 4 + i;
#pragma unroll
        for (int j = 0; j < 4; ++j) {
            const int col = tc * 4 + j;
            g_lg[(size_t)row * 64 + col] = acc[i][j] + g_bg[col];
        }
    }
}

// Top-2 + softmax + per-expert list build. Block-aggregated counters.
__global__ __launch_bounds__(256)
void topk_kernel()
{
    __shared__ int s_local[NE];
    __shared__ int s_base[NE];
    const int t = threadIdx.x;
    const int token = blockIdx.x * 256 + t;
    if (t < NE) s_local[t] = 0;
    __syncthreads();

    const float* l = g_lg + (size_t)token * NE;
    float v[NE];
    const float4 a = *reinterpret_cast<const float4*>(l);
    const float4 b = *reinterpret_cast<const float4*>(l + 4);
    v[0] = a.x; v[1] = a.y; v[2] = a.z; v[3] = a.w;
    v[4] = b.x; v[5] = b.y; v[6] = b.z; v[7] = b.w;

    float v0 = -1e30f, v1 = -1e30f;
    int i0 = 0, i1 = 0;
#pragma unroll
    for (int e = 0; e < NE; ++e)
        if (v[e] > v0) { v0 = v[e]; i0 = e; }
#pragma unroll
    for (int e = 0; e < NE; ++e)
        if (e != i0 && v[e] > v1) { v1 = v[e]; i1 = e; }
    const float w0 = 1.f / (1.f + expf(v1 - v0));
    const float w1 = 1.f - w0;

    const int p0 = atomicAdd(&s_local[i0], 1);
    const int p1 = atomicAdd(&s_local[i1], 1);
    __syncthreads();
    if (t < NE) s_base[t] = atomicAdd(&g_cnt[t], s_local[t]);
    __syncthreads();

    const int q0 = s_base[i0] + p0;
    g_elist[i0 * NT + q0] = token * 2;     g_ew[i0 * NT + q0] = w0;
    const int q1 = s_base[i1] + p1;
    g_elist[i1 * NT + q1] = token * 2 + 1; g_ew[i1 * NT + q1] = w1;
}

// ===========================================================================
// Momentum + LayerNorm. Sums the two expert slots (no atomic accumulation).
// ===========================================================================
__global__ __launch_bounds__(256)
void ln_mom_kernel(const float* __restrict__ mom_in,
                   const float* __restrict__ ln_g, const float* __restrict__ ln_b,
                   float* __restrict__ mom_out, int write_mom)
{
    const int tid = threadIdx.x;
    const int lane = tid & 31, warp = tid >> 5;
    const int token = blockIdx.x * 8 + warp;
    const size_t base = (size_t)token * NHD + lane * 4;
    const size_t base2 = (size_t)token * 2 * NHD + lane * 4;

    const float4 tv = *reinterpret_cast<const float4*>(g_t + base);
    const float4 e0 = *reinterpret_cast<const float4*>(g_eo2 + base2);
    const float4 e1 = *reinterpret_cast<const float4*>(g_eo2 + base2 + NHD);
    const float4 mv = *reinterpret_cast<const float4*>(mom_in + base);

    float nm[4] = { -(e0.x + e1.x) + MU_C * mv.x, -(e0.y + e1.y) + MU_C * mv.y,
                    -(e0.z + e1.z) + MU_C * mv.z, -(e0.w + e1.w) + MU_C * mv.w };
    if (write_mom) {
        float4 o; o.x = nm[0]; o.y = nm[1]; o.z = nm[2]; o.w = nm[3];
        *reinterpret_cast<float4*>(mom_out + base) = o;
    }

    float o[4] = { tv.x + nm[0], tv.y + nm[1], tv.z + nm[2], tv.w + nm[3] };
    float s1 = o[0] + o[1] + o[2] + o[3];
    float s2 = o[0] * o[0] + o[1] * o[1] + o[2] * o[2] + o[3] * o[3];
#pragma unroll
    for (int off = 16; off; off >>= 1) {
        s1 += __shfl_xor_sync(0xffffffffu, s1, off);
        s2 += __shfl_xor_sync(0xffffffffu, s2, off);
    }
    const float mean = s1 * (1.f / NHD);
    const float var  = s2 * (1.f / NHD) - mean * mean;
    const float rstd = rsqrtf(var + LN_EPS_C);

    const float4 gv = *reinterpret_cast<const float4*>(ln_g + lane * 4);
    const float4 bv = *reinterpret_cast<const float4*>(ln_b + lane * 4);
    float4 r;
    r.x = (o[0] - mean) * rstd * gv.x + bv.x;
    r.y = (o[1] - mean) * rstd * gv.y + bv.y;
    r.z = (o[2] - mean) * rstd * gv.z + bv.z;
    r.w = (o[3] - mean) * rstd * gv.w + bv.w;
    *reinterpret_cast<float4*>(g_ln + base) = r;
}

// ---------------------------------------------------------------------------
extern "C" void kernel_launch(void* const* d_in, const int* in_sizes, int n_in,
                              void* d_out, int out_size)
{
    const float* x       = (const float*)d_in[0];
    const float* mom_in  = (const float*)d_in[1];
    const float* split_W = (const float*)d_in[2];
    const float* split_b = (const float*)d_in[3];
    const float* gate_W  = (const float*)d_in[4];
    const float* gate_b  = (const float*)d_in[5];
    const float* W1      = (const float*)d_in[6];
    const float* b1      = (const float*)d_in[7];
    const float* W2      = (const float*)d_in[8];
    const float* b2      = (const float*)d_in[9];
    const float* ln_g    = (const float*)d_in[10];
    const float* ln_b    = (const float*)d_in[11];
    const float* merge_W = (const float*)d_in[12];
    const float* merge_b = (const float*)d_in[13];

    float* out = (float*)d_out;
    const int write_mom = (out_size >= 2 * NROWS * ND) ? 1 : 0;
    float* mom_out = out + (size_t)NROWS * ND;

    void *p_cnt = nullptr, *p_t = nullptr, *p_ln = nullptr;
    cudaGetSymbolAddress(&p_cnt, g_cnt);
    cudaGetSymbolAddress(&p_t, g_t);
    cudaGetSymbolAddress(&p_ln, g_ln);

    cudaMemsetAsync(p_cnt, 0, sizeof(int) * NE);

    cudaFuncSetAttribute(expert_kernel, cudaFuncAttributeMaxDynamicSharedMemorySize,
                         E_SMEM_BYTES);
    cudaFuncSetAttribute(mma_gemm_kernel, cudaFuncAttributeMaxDynamicSharedMemorySize,
                         GSMEM_BYTES);

    // Exact-fp32 gate routing
    mg_prep_kernel<<<256, 256>>>(split_W, gate_W);
    gate_bias_kernel<<<1, 64>>>(split_b, gate_W, gate_b);
    gate_gemm_kernel<<<NROWS / 64, 256>>>(x);
    topk_kernel<<<NT / 256, 256>>>();

    // split: t = x @ split_W + split_b
    mma_gemm_kernel<<<dim3(ND / 128, NROWS / 128), 256, GSMEM_BYTES>>>(
        x, split_W, split_b, (float*)p_t, NROWS, ND, ND);

    // sparse expert compute (top-2 only)
    expert_kernel<<<dim3(NT / 128, NE), 256, E_SMEM_BYTES>>>(W1, b1, W2, b2);

    // momentum + layernorm
    ln_mom_kernel<<<NT / 8, 256>>>(mom_in, ln_g, ln_b, mom_out, write_mom);

    // merge: final = ln_out @ merge_W + merge_b
    mma_gemm_kernel<<<dim3(ND / 128, NROWS / 128), 256, GSMEM_BYTES>>>(
        (const float*)p_ln, merge_W, merge_b, out, NROWS, ND, ND);
}

// round 6
// speedup vs baseline: 2.2538x; 1.0978x over previous
#include <cuda_runtime.h>
#include <math.h>
#include <stdint.h>

// Problem constants
#define NB 4
#define NS 2048
#define ND 1024
#define NH 8
#define NHD 128
#define NFF 512
#define NE 8
#define NT 65536            // B*S*H token-heads
#define NROWS 8192          // B*S
#define MU_C 0.7f
#define LN_EPS_C 1e-5f

// Scratch (static device globals)
__device__ float g_t[(size_t)NROWS * ND];     // split output (exact), for ln_mom
__device__ float g_tr[(size_t)NROWS * ND];    // split output tf32-rounded, for experts
__device__ float g_eo2[(size_t)NT * 2 * NHD]; // expert outputs, 2 slots/token
__device__ float g_ln[(size_t)NROWS * ND];    // post-LN (tf32-rounded), input to merge
__device__ float g_lg[(size_t)NT * NE];       // gate logits [T][E]
__device__ float g_mg[ND * NH * NE];          // fused gate matrix [D][64]
__device__ float g_bg[NH * NE];               // fused gate bias  [64]
__device__ float g_x32[(size_t)NROWS * ND];   // x tf32-rounded
__device__ float g_ws[ND * ND];               // split_W rounded
__device__ float g_wm[ND * ND];               // merge_W rounded
__device__ float g_w1r[NE * NHD * NFF];       // W1 rounded
__device__ float g_w2r[NE * NFF * NHD];       // W2 rounded
__device__ int   g_cnt[NE];
__device__ int   g_elist[NE * NT];            // token*2 + slot
__device__ float g_ew[NE * NT];

// ===========================================================================
// Helpers
// ===========================================================================
__device__ __forceinline__ uint32_t f2tf32(float v) {
    uint32_t o;
    asm("cvt.rna.tf32.f32 %0, %1;" : "=r"(o) : "f"(v));
    return o;
}
__device__ __forceinline__ float rtf(float v) { return __uint_as_float(f2tf32(v)); }

__device__ __forceinline__ void cp16(uint32_t smem, const void* g) {
    asm volatile("cp.async.cg.shared.global [%0], [%1], 16;"
                 :: "r"(smem), "l"(g) : "memory");
}
__device__ __forceinline__ void cp_commit() {
    asm volatile("cp.async.commit_group;" ::: "memory");
}
template <int N>
__device__ __forceinline__ void cp_wait() {
    asm volatile("cp.async.wait_group %0;" :: "n"(N) : "memory");
}

__device__ __forceinline__ void mma8(float* c, const uint32_t* a, const uint32_t* b) {
    asm volatile(
        "mma.sync.aligned.m16n8k8.row.col.f32.tf32.tf32.f32 "
        "{%0,%1,%2,%3}, {%4,%5,%6,%7}, {%8,%9}, {%0,%1,%2,%3};"
        : "+f"(c[0]), "+f"(c[1]), "+f"(c[2]), "+f"(c[3])
        : "r"(a[0]), "r"(a[1]), "r"(a[2]), "r"(a[3]), "r"(b[0]), "r"(b[1]));
}

// One k8 step for a 64x32 warp tile (4 m16 x 4 n8 fragments).
__device__ __forceinline__ void mma_tile_step(
    const uint32_t* __restrict__ As, int lda, int a_k,
    const uint32_t* __restrict__ Bs, int ldb, int b_k,
    int warp_m, int warp_n, int gid, int tig, float acc[4][4][4])
{
    uint32_t a[4][4], b[4][2];
#pragma unroll
    for (int mt = 0; mt < 4; ++mt) {
        const uint32_t* p = As + (warp_m + mt * 16 + gid) * lda + a_k + tig;
        a[mt][0] = p[0];
        a[mt][1] = p[8 * lda];
        a[mt][2] = p[4];
        a[mt][3] = p[8 * lda + 4];
    }
#pragma unroll
    for (int nt = 0; nt < 4; ++nt) {
        const uint32_t* p = Bs + (b_k + tig) * ldb + warp_n + nt * 8 + gid;
        b[nt][0] = p[0];
        b[nt][1] = p[4 * ldb];
    }
#pragma unroll
    for (int mt = 0; mt < 4; ++mt)
#pragma unroll
        for (int nt = 0; nt < 4; ++nt)
            mma8(acc[mt][nt], a[mt], b[nt]);
}

extern __shared__ char dynsm[];

// ===========================================================================
// Rounding pass: tf32-round x, split_W, merge_W, W1, W2 into global copies.
// ===========================================================================
#define SEG0 2097152u            // x        (float4 count)
#define SEG1 (SEG0 + 262144u)    // split_W
#define SEG2 (SEG1 + 262144u)    // merge_W
#define SEG3 (SEG2 + 131072u)    // W1
#define SEG4 (SEG3 + 131072u)    // W2  (total)

__device__ __forceinline__ float4 round4(float4 v) {
    float4 o;
    o.x = rtf(v.x); o.y = rtf(v.y); o.z = rtf(v.z); o.w = rtf(v.w);
    return o;
}

__global__ __launch_bounds__(256)
void round_all_kernel(const float* __restrict__ x, const float* __restrict__ sW,
                      const float* __restrict__ mW, const float* __restrict__ W1,
                      const float* __restrict__ W2)
{
    const uint32_t stride = gridDim.x * 256;
    for (uint32_t i = blockIdx.x * 256 + threadIdx.x; i < SEG4; i += stride) {
        if (i < SEG0) {
            reinterpret_cast<float4*>(g_x32)[i] =
                round4(reinterpret_cast<const float4*>(x)[i]);
        } else if (i < SEG1) {
            const uint32_t j = i - SEG0;
            reinterpret_cast<float4*>(g_ws)[j] =
                round4(reinterpret_cast<const float4*>(sW)[j]);
        } else if (i < SEG2) {
            const uint32_t j = i - SEG1;
            reinterpret_cast<float4*>(g_wm)[j] =
                round4(reinterpret_cast<const float4*>(mW)[j]);
        } else if (i < SEG3) {
            const uint32_t j = i - SEG2;
            reinterpret_cast<float4*>(g_w1r)[j] =
                round4(reinterpret_cast<const float4*>(W1)[j]);
        } else {
            const uint32_t j = i - SEG3;
            reinterpret_cast<float4*>(g_w2r)[j] =
                round4(reinterpret_cast<const float4*>(W2)[j]);
        }
    }
}

// ===========================================================================
// Warp-MMA tf32 GEMM, pre-rounded operands, 3-stage cp.async pipeline.
// C[M,N] = A[M,K] @ B[K,N] + bias[N]; optional C2 = tf32-rounded copy of C.
// CTA 128x128, BK=16, 256 threads (8 warps 2x4).
// ===========================================================================
#define GLDA 20
#define GLDB 132
#define STG_A_W (128 * GLDA)             // 2560 words
#define STG_W   (STG_A_W + 16 * GLDB)    // 4672 words per stage
#define GSMEM_BYTES (3 * STG_W * 4)      // 56064 B

__global__ __launch_bounds__(256, 2)
void mma_gemm_cp(const float* __restrict__ A, const float* __restrict__ B,
                 const float* __restrict__ bias, float* __restrict__ C,
                 float* __restrict__ C2, int M, int N, int K)
{
    uint32_t* smu = reinterpret_cast<uint32_t*>(dynsm);
    const uint32_t sb = (uint32_t)__cvta_generic_to_shared(dynsm);
    const int t = threadIdx.x;
    const int wid = t >> 5, lane = t & 31;
    const int gid = lane >> 2, tig = lane & 3;
    const int warp_m = (wid >> 2) * 64, warp_n = (wid & 3) * 32;
    const int m0 = blockIdx.y * 128, n0 = blockIdx.x * 128;

    const int ar = t >> 1, akc = (t & 1) * 8;
    const int bkr = t >> 4, bnc = (t & 15) * 8;
    const float* Ap = A + (size_t)(m0 + ar) * K + akc;
    const float* Bp = B + (size_t)bkr * N + n0 + bnc;
    const uint32_t a_dst = sb + (uint32_t)(ar * GLDA + akc) * 4;
    const uint32_t b_dst = sb + (uint32_t)(STG_A_W + bkr * GLDB + bnc) * 4;

    float acc[4][4][4];
#pragma unroll
    for (int i = 0; i < 4; ++i)
#pragma unroll
        for (int j = 0; j < 4; ++j)
#pragma unroll
            for (int k = 0; k < 4; ++k) acc[i][j][k] = 0.f;

    const int KI = K >> 4;
#define G_ISSUE(it) do {                                              \
        const int s_ = (it) % 3;                                      \
        const uint32_t so_ = (uint32_t)(s_ * STG_W) * 4;              \
        const float* ag_ = Ap + (size_t)(it) * 16;                    \
        const float* bg_ = Bp + (size_t)(it) * 16 * N;                \
        cp16(a_dst + so_, ag_); cp16(a_dst + so_ + 16, ag_ + 4);      \
        cp16(b_dst + so_, bg_); cp16(b_dst + so_ + 16, bg_ + 4);      \
        cp_commit();                                                  \
    } while (0)

    G_ISSUE(0);
    G_ISSUE(1);

    for (int it = 0; it < KI; ++it) {
        if (it < KI - 1) cp_wait<1>(); else cp_wait<0>();
        __syncthreads();
        if (it + 2 < KI) G_ISSUE(it + 2);
        const int s = it % 3;
        const uint32_t* As = smu + s * STG_W;
        const uint32_t* Bs = As + STG_A_W;
        mma_tile_step(As, GLDA, 0, Bs, GLDB, 0, warp_m, warp_n, gid, tig, acc);
        mma_tile_step(As, GLDA, 8, Bs, GLDB, 8, warp_m, warp_n, gid, tig, acc);
    }
#undef G_ISSUE

    // Epilogue
#pragma unroll
    for (int mt = 0; mt < 4; ++mt) {
        const int r0 = m0 + warp_m + mt * 16 + gid;
        const int r1 = r0 + 8;
#pragma unroll
        for (int nt = 0; nt < 4; ++nt) {
            const int col = n0 + warp_n + nt * 8 + 2 * tig;
            const float b0v = bias[col], b1v = bias[col + 1];
            float2 s0, s1;
            s0.x = acc[mt][nt][0] + b0v; s0.y = acc[mt][nt][1] + b1v;
            s1.x = acc[mt][nt][2] + b0v; s1.y = acc[mt][nt][3] + b1v;
            *reinterpret_cast<float2*>(C + (size_t)r0 * N + col) = s0;
            *reinterpret_cast<float2*>(C + (size_t)r1 * N + col) = s1;
            if (C2) {
                float2 q0, q1;
                q0.x = rtf(s0.x); q0.y = rtf(s0.y);
                q1.x = rtf(s1.x); q1.y = rtf(s1.y);
                *reinterpret_cast<float2*>(C2 + (size_t)r0 * N + col) = q0;
                *reinterpret_cast<float2*>(C2 + (size_t)r1 * N + col) = q1;
            }
        }
    }
}

// ===========================================================================
// Expert kernel: warp MMA, cp.async weight ring (3 bufs) + cp.async A gather.
// Block = (expert e, tile of 128 tokens); plain STG to per-slot rows.
// ===========================================================================
#define ELD 132
#define E_AT 0
#define E_H  16896
#define E_W  33792
#define E_WBUF 4224
#define E_ROW (E_W + 3 * E_WBUF)        // 46464
#define E_GW  (E_ROW + 128)             // 46592
#define E_SMEM_BYTES ((E_GW + 128) * 4) // 186880 B

__global__ __launch_bounds__(256, 1)
void expert_kernel(const float* __restrict__ b1, const float* __restrict__ b2)
{
    uint32_t* smu = reinterpret_cast<uint32_t*>(dynsm);
    const uint32_t sb = (uint32_t)__cvta_generic_to_shared(dynsm);
    uint32_t* sAt = smu + E_AT;
    uint32_t* sH  = smu + E_H;
    int*   srow = reinterpret_cast<int*>(smu + E_ROW);
    float* sgw  = reinterpret_cast<float*>(smu + E_GW);

    const int e  = blockIdx.y;
    const int tb = blockIdx.x * 128;
    const int cnt = g_cnt[e];
    if (tb >= cnt) return;
    const int nrows = min(128, cnt - tb);
    const int t = threadIdx.x;
    const int wid = t >> 5, lane = t & 31;
    const int gid = lane >> 2, tig = lane & 3;
    const int warp_m = (wid >> 2) * 64, warp_n = (wid & 3) * 32;

    if (t < 128) {
        const bool v = t < nrows;
        srow[t] = v ? g_elist[e * NT + tb + t] : -1;   // token*2 + slot
        sgw[t]  = v ? g_ew[e * NT + tb + t] : 0.f;
    }
    __syncthreads();

    // A gather via cp.async from pre-rounded g_tr (group 0)
    {
        const int m = t >> 1, k0 = (t & 1) * 64;
        const int r = srow[m];
        const int token = (r < 0) ? 0 : (r >> 1);
        const float* src = g_tr + (size_t)token * NHD + k0;
        const uint32_t dst = sb + (uint32_t)(E_AT + m * ELD + k0) * 4;
#pragma unroll
        for (int i = 0; i < 16; ++i) cp16(dst + i * 16, src + i * 4);
        cp_commit();
    }

    // W slice mapping: 32 rows x 128 cols per slice
    const int wkr = t >> 3, wnc = (t & 7) * 16;
    const uint32_t w_dst0 = sb + (uint32_t)(E_W + wkr * ELD + wnc) * 4;

#define W_ISSUE(base, stride, slice, buf) do {                                 \
        const float* src_ = (base) + (size_t)((slice) * 32 + wkr) * (stride) + wnc; \
        const uint32_t d_ = w_dst0 + (uint32_t)((buf) * E_WBUF) * 4;           \
        cp16(d_, src_); cp16(d_ + 16, src_ + 4);                               \
        cp16(d_ + 32, src_ + 8); cp16(d_ + 48, src_ + 12);                     \
        cp_commit();                                                           \
    } while (0)

    float y_acc[4][4][4];
#pragma unroll
    for (int i = 0; i < 4; ++i)
#pragma unroll
        for (int j = 0; j < 4; ++j)
#pragma unroll
            for (int k = 0; k < 4; ++k) y_acc[i][j][k] = 0.f;

    for (int fc = 0; fc < 4; ++fc) {
        const float* w1base = g_w1r + (size_t)e * NHD * NFF + fc * 128;
        const float* w2base = g_w2r + ((size_t)e * NFF + fc * 128) * NHD;

        __syncthreads();   // prior readers of W bufs / sH done

        // ---------------- GEMM1: H = A @ W1c ----------------
        W_ISSUE(w1base, NFF, 0, 0);
        W_ISSUE(w1base, NFF, 1, 1);

        float h_acc[4][4][4];
#pragma unroll
        for (int i = 0; i < 4; ++i)
#pragma unroll
            for (int j = 0; j < 4; ++j)
#pragma unroll
                for (int k = 0; k < 4; ++k) h_acc[i][j][k] = 0.f;

        for (int kt = 0; kt < 4; ++kt) {
            if (kt < 3) cp_wait<1>(); else cp_wait<0>();
            __syncthreads();
            if (kt + 2 < 4) W_ISSUE(w1base, NFF, kt + 2, (kt + 2) % 3);
            const uint32_t* Ws = smu + E_W + (kt % 3) * E_WBUF;
#pragma unroll
            for (int k8 = 0; k8 < 4; ++k8)
                mma_tile_step(sAt, ELD, kt * 32 + k8 * 8, Ws, ELD, k8 * 8,
                              warp_m, warp_n, gid, tig, h_acc);
        }

        // bias + relu -> sH (tf32-rounded)
#pragma unroll
        for (int mt = 0; mt < 4; ++mt) {
            const int r0 = warp_m + mt * 16 + gid;
#pragma unroll
            for (int nt = 0; nt < 4; ++nt) {
                const int col = warp_n + nt * 8 + 2 * tig;
                const float bv0 = b1[e * NFF + fc * 128 + col];
                const float bv1 = b1[e * NFF + fc * 128 + col + 1];
                float v0 = h_acc[mt][nt][0] + bv0; v0 = v0 > 0.f ? v0 : 0.f;
                float v1 = h_acc[mt][nt][1] + bv1; v1 = v1 > 0.f ? v1 : 0.f;
                float v2 = h_acc[mt][nt][2] + bv0; v2 = v2 > 0.f ? v2 : 0.f;
                float v3 = h_acc[mt][nt][3] + bv1; v3 = v3 > 0.f ? v3 : 0.f;
                sH[r0 * ELD + col]           = f2tf32(v0);
                sH[r0 * ELD + col + 1]       = f2tf32(v1);
                sH[(r0 + 8) * ELD + col]     = f2tf32(v2);
                sH[(r0 + 8) * ELD + col + 1] = f2tf32(v3);
            }
        }
        __syncthreads();   // sH complete; all GEMM1 compute done

        // ---------------- GEMM2: Y += H @ W2c ----------------
        W_ISSUE(w2base, NHD, 0, 0);
        W_ISSUE(w2base, NHD, 1, 1);

        for (int kt = 0; kt < 4; ++kt) {
            if (kt < 3) cp_wait<1>(); else cp_wait<0>();
            __syncthreads();
            if (kt + 2 < 4) W_ISSUE(w2base, NHD, kt + 2, (kt + 2) % 3);
            const uint32_t* Ws = smu + E_W + (kt % 3) * E_WBUF;
#pragma unroll
            for (int k8 = 0; k8 < 4; ++k8)
                mma_tile_step(sH, ELD, kt * 32 + k8 * 8, Ws, ELD, k8 * 8,
                              warp_m, warp_n, gid, tig, y_acc);
        }
    }
#undef W_ISSUE

    // Epilogue: plain STG of gate_w * (Y + b2) into per-slot row
#pragma unroll
    for (int mt = 0; mt < 4; ++mt) {
        const int m0_ = warp_m + mt * 16 + gid;
        const int rA = srow[m0_], rB = srow[m0_ + 8];
        const float wA = sgw[m0_], wB = sgw[m0_ + 8];
#pragma unroll
        for (int nt = 0; nt < 4; ++nt) {
            const int col = warp_n + nt * 8 + 2 * tig;
            const float b0v = b2[e * NHD + col];
            const float b1v = b2[e * NHD + col + 1];
            if (rA >= 0) {
                float2 v;
                v.x = wA * (y_acc[mt][nt][0] + b0v);
                v.y = wA * (y_acc[mt][nt][1] + b1v);
                *reinterpret_cast<float2*>(&g_eo2[(size_t)rA * NHD + col]) = v;
            }
            if (rB >= 0) {
                float2 v;
                v.x = wB * (y_acc[mt][nt][2] + b0v);
                v.y = wB * (y_acc[mt][nt][3] + b1v);
                *reinterpret_cast<float2*>(&g_eo2[(size_t)rB * NHD + col]) = v;
            }
        }
    }
}

// ===========================================================================
// Gate path (exact fp32 routing). mg_prep and gate_bias merged.
// ===========================================================================
__global__ __launch_bounds__(256)
void mg_prep_bias_kernel(const float* __restrict__ sW, const float* __restrict__ gW,
                         const float* __restrict__ sb_, const float* __restrict__ gb)
{
    __shared__ float sg[NHD * NE];
    const int tid = threadIdx.x;
    for (int i = tid; i < NHD * NE; i += 256) sg[i] = gW[i];
    __syncthreads();

    if (blockIdx.x == 256) {       // bias block
        if (tid < 64) {
            const int h = tid >> 3, e = tid & 7;
            float s = gb[e];
            for (int j = 0; j < NHD; ++j) s += sb_[h * NHD + j] * sg[j * NE + e];
            g_bg[tid] = s;
        }
        return;
    }
    const int idx = blockIdx.x * 256 + tid;
    const int d = idx >> 6, he = idx & 63;
    const int h = he >> 3, e = he & 7;
    const float* wrow = sW + (size_t)d * ND + h * NHD;
    float s = 0.f;
#pragma unroll 8
    for (int j = 0; j < NHD; ++j) s += wrow[j] * sg[j * NE + e];
    g_mg[d * 64 + he] = s;
}

__global__ __launch_bounds__(256, 2)
void gate_gemm_kernel(const float* __restrict__ A)
{
    __shared__ float As[16][64];
    __shared__ float Bs[16][64];
    const int m0 = blockIdx.x * 64;
    const int t = threadIdx.x;
    const int tr = t >> 4, tc = t & 15;

    float acc[4][4];
#pragma unroll
    for (int i = 0; i < 4; ++i)
#pragma unroll
        for (int j = 0; j < 4; ++j) acc[i][j] = 0.f;

    for (int k0 = 0; k0 < ND; k0 += 16) {
        {
            const int row = t >> 2, kc = (t & 3) * 4;
            const float4 v = *reinterpret_cast<const float4*>(
                A + (size_t)(m0 + row) * ND + k0 + kc);
            As[kc + 0][row] = v.x; As[kc + 1][row] = v.y;
            As[kc + 2][row] = v.z; As[kc + 3][row] = v.w;
        }
        {
            const int row = t >> 4, col = (t & 15) * 4;
            *reinterpret_cast<float4*>(&Bs[row][col]) =
                *reinterpret_cast<const float4*>(g_mg + (size_t)(k0 + row) * 64 + col);
        }
        __syncthreads();
#pragma unroll
        for (int kk = 0; kk < 16; ++kk) {
            float ra[4], rb[4];
            *reinterpret_cast<float4*>(ra) = *reinterpret_cast<const float4*>(&As[kk][tr * 4]);
            *reinterpret_cast<float4*>(rb) = *reinterpret_cast<const float4*>(&Bs[kk][tc * 4]);
#pragma unroll
            for (int i = 0; i < 4; ++i)
#pragma unroll
                for (int j = 0; j < 4; ++j)
                    acc[i][j] += ra[i] * rb[j];
        }
        __syncthreads();
    }
#pragma unroll
    for (int i = 0; i < 4; ++i) {
        const int row = m0 + tr * 4 + i;
#pragma unroll
        for (int j = 0; j < 4; ++j) {
            const int col = tc * 4 + j;
            g_lg[(size_t)row * 64 + col] = acc[i][j] + g_bg[col];
        }
    }
}

// Top-2 + softmax + per-expert list build. Block-aggregated counters.
__global__ __launch_bounds__(256)
void topk_kernel()
{
    __shared__ int s_local[NE];
    __shared__ int s_base[NE];
    const int t = threadIdx.x;
    const int token = blockIdx.x * 256 + t;
    if (t < NE) s_local[t] = 0;
    __syncthreads();

    const float* l = g_lg + (size_t)token * NE;
    float v[NE];
    const float4 a = *reinterpret_cast<const float4*>(l);
    const float4 b = *reinterpret_cast<const float4*>(l + 4);
    v[0] = a.x; v[1] = a.y; v[2] = a.z; v[3] = a.w;
    v[4] = b.x; v[5] = b.y; v[6] = b.z; v[7] = b.w;

    float v0 = -1e30f, v1 = -1e30f;
    int i0 = 0, i1 = 0;
#pragma unroll
    for (int e = 0; e < NE; ++e)
        if (v[e] > v0) { v0 = v[e]; i0 = e; }
#pragma unroll
    for (int e = 0; e < NE; ++e)
        if (e != i0 && v[e] > v1) { v1 = v[e]; i1 = e; }
    const float w0 = 1.f / (1.f + expf(v1 - v0));
    const float w1 = 1.f - w0;

    const int p0 = atomicAdd(&s_local[i0], 1);
    const int p1 = atomicAdd(&s_local[i1], 1);
    __syncthreads();
    if (t < NE) s_base[t] = atomicAdd(&g_cnt[t], s_local[t]);
    __syncthreads();

    const int q0 = s_base[i0] + p0;
    g_elist[i0 * NT + q0] = token * 2;     g_ew[i0 * NT + q0] = w0;
    const int q1 = s_base[i1] + p1;
    g_elist[i1 * NT + q1] = token * 2 + 1; g_ew[i1 * NT + q1] = w1;
}

// ===========================================================================
// Momentum + LayerNorm. Sums the two expert slots; stores g_ln tf32-rounded.
// ===========================================================================
__global__ __launch_bounds__(256)
void ln_mom_kernel(const float* __restrict__ mom_in,
                   const float* __restrict__ ln_g, const float* __restrict__ ln_b,
                   float* __restrict__ mom_out, int write_mom)
{
    const int tid = threadIdx.x;
    const int lane = tid & 31, warp = tid >> 5;
    const int token = blockIdx.x * 8 + warp;
    const size_t base = (size_t)token * NHD + lane * 4;
    const size_t base2 = (size_t)token * 2 * NHD + lane * 4;

    const float4 tv = *reinterpret_cast<const float4*>(g_t + base);
    const float4 e0 = *reinterpret_cast<const float4*>(g_eo2 + base2);
    const float4 e1 = *reinterpret_cast<const float4*>(g_eo2 + base2 + NHD);
    const float4 mv = *reinterpret_cast<const float4*>(mom_in + base);

    float nm[4] = { -(e0.x + e1.x) + MU_C * mv.x, -(e0.y + e1.y) + MU_C * mv.y,
                    -(e0.z + e1.z) + MU_C * mv.z, -(e0.w + e1.w) + MU_C * mv.w };
    if (write_mom) {
        float4 o; o.x = nm[0]; o.y = nm[1]; o.z = nm[2]; o.w = nm[3];
        *reinterpret_cast<float4*>(mom_out + base) = o;
    }

    float o[4] = { tv.x + nm[0], tv.y + nm[1], tv.z + nm[2], tv.w + nm[3] };
    float s1 = o[0] + o[1] + o[2] + o[3];
    float s2 = o[0] * o[0] + o[1] * o[1] + o[2] * o[2] + o[3] * o[3];
#pragma unroll
    for (int off = 16; off; off >>= 1) {
        s1 += __shfl_xor_sync(0xffffffffu, s1, off);
        s2 += __shfl_xor_sync(0xffffffffu, s2, off);
    }
    const float mean = s1 * (1.f / NHD);
    const float var  = s2 * (1.f / NHD) - mean * mean;
    const float rstd = rsqrtf(var + LN_EPS_C);

    const float4 gv = *reinterpret_cast<const float4*>(ln_g + lane * 4);
    const float4 bv = *reinterpret_cast<const float4*>(ln_b + lane * 4);
    float4 r;
    r.x = rtf((o[0] - mean) * rstd * gv.x + bv.x);
    r.y = rtf((o[1] - mean) * rstd * gv.y + bv.y);
    r.z = rtf((o[2] - mean) * rstd * gv.z + bv.z);
    r.w = rtf((o[3] - mean) * rstd * gv.w + bv.w);
    *reinterpret_cast<float4*>(g_ln + base) = r;
}

// ---------------------------------------------------------------------------
extern "C" void kernel_launch(void* const* d_in, const int* in_sizes, int n_in,
                              void* d_out, int out_size)
{
    const float* x       = (const float*)d_in[0];
    const float* mom_in  = (const float*)d_in[1];
    const float* split_W = (const float*)d_in[2];
    const float* split_b = (const float*)d_in[3];
    const float* gate_W  = (const float*)d_in[4];
    const float* gate_b  = (const float*)d_in[5];
    const float* W1      = (const float*)d_in[6];
    const float* b1      = (const float*)d_in[7];
    const float* W2      = (const float*)d_in[8];
    const float* b2      = (const float*)d_in[9];
    const float* ln_g    = (const float*)d_in[10];
    const float* ln_b    = (const float*)d_in[11];
    const float* merge_W = (const float*)d_in[12];
    const float* merge_b = (const float*)d_in[13];

    float* out = (float*)d_out;
    const int write_mom = (out_size >= 2 * NROWS * ND) ? 1 : 0;
    float* mom_out = out + (size_t)NROWS * ND;

    void *p_cnt = nullptr, *p_t = nullptr, *p_tr = nullptr, *p_ln = nullptr;
    void *p_x32 = nullptr, *p_ws = nullptr, *p_wm = nullptr;
    cudaGetSymbolAddress(&p_cnt, g_cnt);
    cudaGetSymbolAddress(&p_t, g_t);
    cudaGetSymbolAddress(&p_tr, g_tr);
    cudaGetSymbolAddress(&p_ln, g_ln);
    cudaGetSymbolAddress(&p_x32, g_x32);
    cudaGetSymbolAddress(&p_ws, g_ws);
    cudaGetSymbolAddress(&p_wm, g_wm);

    cudaMemsetAsync(p_cnt, 0, sizeof(int) * NE);

    cudaFuncSetAttribute(expert_kernel, cudaFuncAttributeMaxDynamicSharedMemorySize,
                         E_SMEM_BYTES);
    cudaFuncSetAttribute(mma_gemm_cp, cudaFuncAttributeMaxDynamicSharedMemorySize,
                         GSMEM_BYTES);

    // tf32 pre-rounding pass
    round_all_kernel<<<2048, 256>>>(x, split_W, merge_W, W1, W2);

    // Exact-fp32 gate routing
    mg_prep_bias_kernel<<<257, 256>>>(split_W, gate_W, split_b, gate_b);
    gate_gemm_kernel<<<NROWS / 64, 256>>>(x);

    // split: t = x @ split_W + split_b  (writes exact g_t + rounded g_tr)
    mma_gemm_cp<<<dim3(ND / 128, NROWS / 128), 256, GSMEM_BYTES>>>(
        (const float*)p_x32, (const float*)p_ws, split_b, (float*)p_t,
        (float*)p_tr, NROWS, ND, ND);

    topk_kernel<<<NT / 256, 256>>>();

    // sparse expert compute (top-2 only)
    expert_kernel<<<dim3(NT / 128, NE), 256, E_SMEM_BYTES>>>(b1, b2);

    // momentum + layernorm (stores g_ln tf32-rounded)
    ln_mom_kernel<<<NT / 8, 256>>>(mom_in, ln_g, ln_b, mom_out, write_mom);

    // merge: final = ln_out @ merge_W + merge_b
    mma_gemm_cp<<<dim3(ND / 128, NROWS / 128), 256, GSMEM_BYTES>>>(
        (const float*)p_ln, (const float*)p_wm, merge_b, out,
        nullptr, NROWS, ND, ND);
}